// round 2
// baseline (speedup 1.0000x reference)
#include <cuda_runtime.h>
#include <math.h>

#define Bz 32
#define Sz 512
#define NB 20
#define EMB 128
#define INNER 128
#define VOCAB 40000
#define QL 20

typedef unsigned long long u64;

// ---- packed f32x2 helpers (FFMA2 path; ptxas never auto-emits this) ----
__device__ __forceinline__ u64 dup2(float a) {
    u64 r; asm("mov.b64 %0, {%1, %1};" : "=l"(r) : "f"(a)); return r;
}
__device__ __forceinline__ u64 pack2(float x, float y) {
    u64 r; asm("mov.b64 %0, {%1, %2};" : "=l"(r) : "f"(x), "f"(y)); return r;
}
__device__ __forceinline__ float2 unpack2(u64 v) {
    float2 f; asm("mov.b64 {%0, %1}, %2;" : "=f"(f.x), "=f"(f.y) : "l"(v)); return f;
}
__device__ __forceinline__ void ffma2(u64& d, u64 a, u64 b) {
    asm("fma.rn.f32x2 %0, %1, %2, %0;" : "+l"(d) : "l"(a), "l"(b));
}
__device__ __forceinline__ float neg_inf_f() { return __int_as_float(0xff800000); }

// ---- scratch (device globals; no allocation allowed) ----
__device__ float g_qc[Bz * INNER];
__device__ float g_tfv[Bz * INNER];
__device__ float g_uH[Bz * EMB];
__device__ float g_kb[NB * INNER];
__device__ u64   g_DE[EMB * INNER];          // interleaved (D[e][i], E[e][i])
__device__ float g_tm[Bz * Sz * EMB];        // temporal_memory, 8 MB
__device__ float g_talign[Bz * Sz];          // unmasked temporal align
__device__ float g_ob[Bz * EMB];             // o + u@H

// ============================================================
// prep: u[b] = sum_q emb[queries]*mult_mask ; qc = u@C ; tf = u@F ; uH = u@H
// grid Bz x 128
// ============================================================
__global__ void __launch_bounds__(128) k_prep(
    const int* __restrict__ queries, const float* __restrict__ emb,
    const float* __restrict__ mmask, const float* __restrict__ C,
    const float* __restrict__ F, const float* __restrict__ H)
{
    const int b = blockIdx.x, tid = threadIdx.x;
    __shared__ float su[EMB];
    float u = 0.f;
#pragma unroll
    for (int q = 0; q < QL; q++)
        u += emb[(size_t)queries[b * QL + q] * EMB + tid] * mmask[q * EMB + tid];
    su[tid] = u;
    __syncthreads();
    float c = 0.f, f = 0.f, h = 0.f;
#pragma unroll 4
    for (int e = 0; e < EMB; e++) {
        const float ue = su[e];
        c += ue * C[e * INNER + tid];
        f += ue * F[e * INNER + tid];
        h += ue * H[e * EMB + tid];
    }
    g_qc[b * INNER + tid]  = c;
    g_tfv[b * INNER + tid] = f;
    g_uH[b * EMB + tid]    = h;
}

// ============================================================
// kb[n] = emb[keys[n]] @ Bm       grid NB x 128
// ============================================================
__global__ void __launch_bounds__(128) k_kb(
    const int* __restrict__ keys, const float* __restrict__ emb,
    const float* __restrict__ Bm)
{
    const int n = blockIdx.x, tid = threadIdx.x;
    __shared__ float se[EMB];
    se[tid] = emb[(size_t)keys[n] * EMB + tid];
    __syncthreads();
    float a = 0.f;
#pragma unroll 4
    for (int e = 0; e < EMB; e++) a += se[e] * Bm[e * INNER + tid];
    g_kb[n * INNER + tid] = a;
}

// ============================================================
// interleave D,E into float2 pairs    grid 128 x 128
// ============================================================
__global__ void __launch_bounds__(128) k_de(const float* __restrict__ D,
                                            const float* __restrict__ E)
{
    const int i = blockIdx.x * 128 + threadIdx.x;
    g_DE[i] = pack2(D[i], E[i]);
}

// ============================================================
// main fused kernel: per (b,s) — ia GEMM (FFMA2), tanh, intratemporal
// softmax over NB, temporal_memory. grid (Sz, Bz) x 128
// ============================================================
__global__ void __launch_bounds__(128) k_main(
    const float* __restrict__ mem, const float* __restrict__ A,
    const float* __restrict__ v)
{
    const int s = blockIdx.x, b = blockIdx.y;
    const int tid = threadIdx.x, lane = tid & 31, wid = tid >> 5;

    __shared__ float smem_t[EMB * NB];   // [e][n], 80B per e-row (16B aligned)
    __shared__ float s_part[4 * NB];
    __shared__ float s_align[NB];

    // load memories tile transposed to [e][n]
    const float* mp = mem + ((size_t)(b * Sz + s)) * NB * EMB;
#pragma unroll
    for (int r = 0; r < NB; r++)
        smem_t[tid * NB + r] = mp[r * EMB + tid];
    __syncthreads();

    // ---- phase A: ia[n][i] for this thread's column i=tid, all n ----
    u64 acc[NB / 2];
#pragma unroll
    for (int j = 0; j < NB / 2; j++) acc[j] = 0ull;

#pragma unroll 4
    for (int e = 0; e < EMB; e++) {
        const u64 ad = dup2(A[e * INNER + tid]);
        const ulonglong2* row = (const ulonglong2*)(smem_t + e * NB);
#pragma unroll
        for (int k = 0; k < 5; k++) {
            const ulonglong2 m = row[k];
            ffma2(acc[2 * k],     ad, m.x);
            ffma2(acc[2 * k + 1], ad, m.y);
        }
    }

    // ---- tanh + v-weighted, reduce over i for each n ----
    const float qci = g_qc[b * INNER + tid];
    const float vi  = v[tid];
    float tv[NB];
#pragma unroll
    for (int j = 0; j < NB / 2; j++) {
        const float2 f = unpack2(acc[j]);
        tv[2 * j]     = vi * tanhf(f.x + g_kb[(2 * j) * INNER + tid] + qci);
        tv[2 * j + 1] = vi * tanhf(f.y + g_kb[(2 * j + 1) * INNER + tid] + qci);
    }
#pragma unroll
    for (int n = 0; n < NB; n++) {
        float t = tv[n];
#pragma unroll
        for (int o = 16; o > 0; o >>= 1) t += __shfl_xor_sync(0xffffffffu, t, o);
        tv[n] = t;
    }
    if (lane == 0) {
#pragma unroll
        for (int n = 0; n < NB; n++) s_part[wid * NB + n] = tv[n];
    }
    __syncthreads();
    if (tid < NB)
        s_align[tid] = s_part[tid] + s_part[NB + tid] + s_part[2 * NB + tid] + s_part[3 * NB + tid];
    __syncthreads();

    // ---- softmax over NB (redundant per-thread, NB=20) ----
    float p[NB];
    float mx = -1e30f;
#pragma unroll
    for (int n = 0; n < NB; n++) { p[n] = s_align[n]; mx = fmaxf(mx, p[n]); }
    float Z = 0.f;
#pragma unroll
    for (int n = 0; n < NB; n++) { p[n] = expf(p[n] - mx); Z += p[n]; }
    const float invZ = 1.f / Z;

    // ---- temporal_memory[e=tid] ----
    float tm = 0.f;
    const float4* r4 = (const float4*)(smem_t + tid * NB);
#pragma unroll
    for (int k = 0; k < 5; k++) {
        const float4 m4 = r4[k];
        tm += p[4 * k] * m4.x + p[4 * k + 1] * m4.y + p[4 * k + 2] * m4.z + p[4 * k + 3] * m4.w;
    }
    tm *= invZ;
    g_tm[((size_t)(b * Sz + s)) * EMB + tid] = tm;
}

// ============================================================
// temporal alignment: talign[b,s] = sum_i w[i]*tanh(tm@D + story@E + tf)
// 16 sentences per CTA to amortize D/E traffic. grid (Sz/16, Bz) x 128
// ============================================================
#define ST 16
__global__ void __launch_bounds__(128) k_align2(
    const float* __restrict__ stories, const float* __restrict__ w)
{
    const int b = blockIdx.y, s0 = blockIdx.x * ST;
    const int tid = threadIdx.x, lane = tid & 31, wid = tid >> 5;

    __shared__ u64 sp[EMB * ST];       // [e][si] = (tm, story)
    __shared__ float s_part[4 * ST];

#pragma unroll
    for (int si = 0; si < ST; si++) {
        const size_t base = ((size_t)(b * Sz + s0 + si)) * EMB + tid;
        sp[tid * ST + si] = pack2(g_tm[base], stories[base]);
    }
    __syncthreads();

    u64 acc[ST];
#pragma unroll
    for (int si = 0; si < ST; si++) acc[si] = 0ull;

#pragma unroll 2
    for (int e = 0; e < EMB; e++) {
        const u64 de = g_DE[e * INNER + tid];
        const ulonglong2* row = (const ulonglong2*)(sp + e * ST);
#pragma unroll
        for (int k = 0; k < ST / 2; k++) {
            const ulonglong2 m = row[k];
            ffma2(acc[2 * k],     m.x, de);
            ffma2(acc[2 * k + 1], m.y, de);
        }
    }

    const float tfi = g_tfv[b * INNER + tid];
    const float wi  = w[tid];
    float tv[ST];
#pragma unroll
    for (int si = 0; si < ST; si++) {
        const float2 f = unpack2(acc[si]);
        float t = wi * tanhf(f.x + f.y + tfi);
#pragma unroll
        for (int o = 16; o > 0; o >>= 1) t += __shfl_xor_sync(0xffffffffu, t, o);
        tv[si] = t;
    }
    if (lane == 0) {
#pragma unroll
        for (int si = 0; si < ST; si++) s_part[wid * ST + si] = tv[si];
    }
    __syncthreads();
    if (tid < ST)
        g_talign[b * Sz + s0 + tid] =
            s_part[tid] + s_part[ST + tid] + s_part[2 * ST + tid] + s_part[3 * ST + tid];
}

// ============================================================
// temporal softmax over S + readout o ; ob = o + u@H. grid Bz x 128
// ============================================================
__global__ void __launch_bounds__(128) k_temporal(const float* __restrict__ mask)
{
    const int b = blockIdx.x, tid = threadIdx.x, lane = tid & 31, wid = tid >> 5;
    __shared__ float sp[Sz];
    __shared__ float sr[4];

    float vals[4];
    float mx = neg_inf_f();
#pragma unroll
    for (int r = 0; r < 4; r++) {
        const int s = r * 128 + tid;
        const float ta = g_talign[b * Sz + s];
        const float m  = mask[b * Sz + s];
        const float ml = (m != 0.f) ? ta * m : neg_inf_f();
        vals[r] = ml;
        mx = fmaxf(mx, ml);
    }
#pragma unroll
    for (int o = 16; o > 0; o >>= 1) mx = fmaxf(mx, __shfl_xor_sync(0xffffffffu, mx, o));
    if (lane == 0) sr[wid] = mx;
    __syncthreads();
    mx = fmaxf(fmaxf(sr[0], sr[1]), fmaxf(sr[2], sr[3]));
    __syncthreads();

    float Z = 0.f;
#pragma unroll
    for (int r = 0; r < 4; r++) {
        const float ev = expf(vals[r] - mx);
        sp[r * 128 + tid] = ev;
        Z += ev;
    }
#pragma unroll
    for (int o = 16; o > 0; o >>= 1) Z += __shfl_xor_sync(0xffffffffu, Z, o);
    if (lane == 0) sr[wid] = Z;
    __syncthreads();
    Z = sr[0] + sr[1] + sr[2] + sr[3];
    const float invZ = 1.f / Z;

    float o_ = 0.f;
    const float* tmb = g_tm + (size_t)b * Sz * EMB + tid;
#pragma unroll 8
    for (int s = 0; s < Sz; s++) o_ += sp[s] * tmb[(size_t)s * EMB];
    g_ob[b * EMB + tid] = o_ * invZ + g_uH[b * EMB + tid];
}

// ============================================================
// logits = ob @ R, b packed in pairs via FFMA2. grid ceil(VOCAB/128) x 128
// ============================================================
__global__ void __launch_bounds__(128) k_logits(const float* __restrict__ R,
                                                float* __restrict__ out)
{
    __shared__ u64 so2[EMB * (Bz / 2)];   // [e][bpair]
    const int tid = threadIdx.x;
#pragma unroll
    for (int r = 0; r < EMB * (Bz / 2) / 128; r++) {
        const int idx = r * 128 + tid;
        const int e = idx >> 4, bb = idx & 15;
        so2[idx] = pack2(g_ob[(2 * bb) * EMB + e], g_ob[(2 * bb + 1) * EMB + e]);
    }
    __syncthreads();

    const int col = blockIdx.x * 128 + tid;
    if (col >= VOCAB) return;

    u64 acc[Bz / 2];
#pragma unroll
    for (int j = 0; j < Bz / 2; j++) acc[j] = 0ull;

#pragma unroll 2
    for (int e = 0; e < EMB; e++) {
        const u64 rd = dup2(R[(size_t)e * VOCAB + col]);
        const u64* row = so2 + e * (Bz / 2);
#pragma unroll
        for (int bb = 0; bb < Bz / 2; bb++) ffma2(acc[bb], rd, row[bb]);
    }
#pragma unroll
    for (int bb = 0; bb < Bz / 2; bb++) {
        const float2 f = unpack2(acc[bb]);
        out[(size_t)(2 * bb) * VOCAB + col]     = f.x;
        out[(size_t)(2 * bb + 1) * VOCAB + col] = f.y;
    }
}

// ============================================================
extern "C" void kernel_launch(void* const* d_in, const int* in_sizes, int n_in,
                              void* d_out, int out_size)
{
    const float* memories = (const float*)d_in[0];
    const float* stories  = (const float*)d_in[1];
    const float* smask    = (const float*)d_in[2];
    const int*   queries  = (const int*)  d_in[3];
    const int*   keys     = (const int*)  d_in[4];
    const float* emb      = (const float*)d_in[5];
    const float* mmask    = (const float*)d_in[6];
    const float* A        = (const float*)d_in[7];
    const float* Bm       = (const float*)d_in[8];
    const float* C        = (const float*)d_in[9];
    const float* v        = (const float*)d_in[10];
    const float* D        = (const float*)d_in[11];
    const float* E        = (const float*)d_in[12];
    const float* F        = (const float*)d_in[13];
    const float* w        = (const float*)d_in[14];
    const float* H        = (const float*)d_in[15];
    const float* R        = (const float*)d_in[16];
    float* out = (float*)d_out;

    k_prep<<<Bz, 128>>>(queries, emb, mmask, C, F, H);
    k_kb<<<NB, 128>>>(keys, emb, Bm);
    k_de<<<EMB * INNER / 128, 128>>>(D, E);
    k_main<<<dim3(Sz, Bz), 128>>>(memories, A, v);
    k_align2<<<dim3(Sz / ST, Bz), 128>>>(stories, w);
    k_temporal<<<Bz, 128>>>(smask);
    k_logits<<<(VOCAB + 127) / 128, 128>>>(R, out);
}

// round 4
// speedup vs baseline: 1.4360x; 1.4360x over previous
#include <cuda_runtime.h>
#include <cuda_bf16.h>
#include <math.h>
#include <stdint.h>

#define Bz 32
#define Sz 512
#define NB 20
#define EMB 128
#define INNER 128
#define VOCAB 40000
#define QL 20
#define NGRP (Bz * Sz)

typedef unsigned long long u64;
typedef unsigned int u32;

// ---- packed f32x2 helpers ----
__device__ __forceinline__ u64 dup2(float a) {
    u64 r; asm("mov.b64 %0, {%1, %1};" : "=l"(r) : "f"(a)); return r;
}
__device__ __forceinline__ u64 pack2(float x, float y) {
    u64 r; asm("mov.b64 %0, {%1, %2};" : "=l"(r) : "f"(x), "f"(y)); return r;
}
__device__ __forceinline__ float2 unpack2(u64 v) {
    float2 f; asm("mov.b64 {%0, %1}, %2;" : "=f"(f.x), "=f"(f.y) : "l"(v)); return f;
}
__device__ __forceinline__ void ffma2(u64& d, u64 a, u64 b) {
    asm("fma.rn.f32x2 %0, %1, %2, %0;" : "+l"(d) : "l"(a), "l"(b));
}
__device__ __forceinline__ float neg_inf_f() { return __int_as_float(0xff800000); }
__device__ __forceinline__ float tanh_fast(float x) {
    float e = __expf(2.f * x);
    return 1.f - __fdividef(2.f, e + 1.f);
}

// ---- scratch ----
__device__ float g_qc[Bz * INNER];
__device__ float g_tfv[Bz * INNER];
__device__ float g_uH[Bz * EMB];
__device__ float g_kb[NB * INNER];
__device__ u64   g_DE[EMB * INNER];
__device__ float g_tm[Bz * Sz * EMB];
__device__ float g_talign[Bz * Sz];
__device__ float g_ob[Bz * EMB];
__device__ unsigned char g_ATsw[69632];   // A^T bf16 hi/lo images, 272B row stride

// ---- warp mma helpers (legacy HMMA path; works on plain sm_103 target) ----
__device__ __forceinline__ u32 smem_u32(const void* p) {
    u32 a; asm("{ .reg .u64 t; cvta.to.shared.u64 t, %1; cvt.u32.u64 %0, t; }" : "=r"(a) : "l"(p));
    return a;
}
__device__ __forceinline__ void ldsm4(u32* r, u32 addr) {
    asm volatile("ldmatrix.sync.aligned.m8n8.x4.shared.b16 {%0,%1,%2,%3}, [%4];"
        : "=r"(r[0]), "=r"(r[1]), "=r"(r[2]), "=r"(r[3]) : "r"(addr));
}
__device__ __forceinline__ void mma16816(float* d, const u32* a, u32 b0, u32 b1) {
    asm volatile("mma.sync.aligned.m16n8k16.row.col.f32.bf16.bf16.f32 "
        "{%0,%1,%2,%3}, {%4,%5,%6,%7}, {%8,%9}, {%0,%1,%2,%3};"
        : "+f"(d[0]), "+f"(d[1]), "+f"(d[2]), "+f"(d[3])
        : "r"(a[0]), "r"(a[1]), "r"(a[2]), "r"(a[3]), "r"(b0), "r"(b1));
}

// smem layout (bytes, from dynamic smem base)
#define IMG    34816            // one 128x136 bf16 image
#define BUFSZ  69632            // hi + lo image
#define AT_OFF 139264           // A^T hi (lo at +IMG)
#define KB_OFF 208896           // kb [20][132] f32
#define QC_OFF 219456           // qc [2][128] f32
#define SV_OFF 220480           // v  [128] f32
#define ALN_OFF 220992          // per-row align [128]
#define SPB_OFF 221504          // per-row softmax prob [128]
#define DYN_SMEM 222016

// ============================================================
__global__ void __launch_bounds__(128) k_prep(
    const int* __restrict__ queries, const float* __restrict__ emb,
    const float* __restrict__ mmask, const float* __restrict__ C,
    const float* __restrict__ F, const float* __restrict__ H)
{
    const int b = blockIdx.x, tid = threadIdx.x;
    __shared__ float su[EMB];
    float u = 0.f;
#pragma unroll
    for (int q = 0; q < QL; q++)
        u += emb[(size_t)queries[b * QL + q] * EMB + tid] * mmask[q * EMB + tid];
    su[tid] = u;
    __syncthreads();
    float c = 0.f, f = 0.f, h = 0.f;
#pragma unroll 4
    for (int e = 0; e < EMB; e++) {
        const float ue = su[e];
        c += ue * C[e * INNER + tid];
        f += ue * F[e * INNER + tid];
        h += ue * H[e * EMB + tid];
    }
    g_qc[b * INNER + tid]  = c;
    g_tfv[b * INNER + tid] = f;
    g_uH[b * EMB + tid]    = h;
}

__global__ void __launch_bounds__(128) k_kb(
    const int* __restrict__ keys, const float* __restrict__ emb,
    const float* __restrict__ Bm)
{
    const int n = blockIdx.x, tid = threadIdx.x;
    __shared__ float se[EMB];
    se[tid] = emb[(size_t)keys[n] * EMB + tid];
    __syncthreads();
    float a = 0.f;
#pragma unroll 4
    for (int e = 0; e < EMB; e++) a += se[e] * Bm[e * INNER + tid];
    g_kb[n * INNER + tid] = a;
}

__global__ void __launch_bounds__(128) k_de(const float* __restrict__ D,
                                            const float* __restrict__ E)
{
    const int i = blockIdx.x * 128 + threadIdx.x;
    g_DE[i] = pack2(D[i], E[i]);
}

// A[e][i] -> A^T bf16 hi/lo images: row=i, col=e, 272B row stride
__global__ void __launch_bounds__(128) k_split(const float* __restrict__ A)
{
    const int idx = blockIdx.x * 128 + threadIdx.x;
    const int e = idx >> 7, i = idx & 127;
    const float x = A[e * 128 + i];
    const __nv_bfloat16 h = __float2bfloat16_rn(x);
    const __nv_bfloat16 l = __float2bfloat16_rn(x - __bfloat162float(h));
    *(unsigned short*)(g_ATsw + i * 272 + e * 2)       = __bfloat16_as_ushort(h);
    *(unsigned short*)(g_ATsw + IMG + i * 272 + e * 2) = __bfloat16_as_ushort(l);
}

// ============================================================
// k_hmma: mma.sync bf16x3 ia-GEMM + NB softmax + temporal_memory
// ============================================================
__device__ __forceinline__ void load_tile(char* sm, const float* __restrict__ mem,
                                          int Gt0, int ng, int buf, int tid)
{
    char* bufp = sm + buf * BUFSZ;
    const float* src = mem + (size_t)Gt0 * (NB * EMB);
    const int iters = ng * 20 * 32;
    for (int idx = tid; idx < iters; idx += 256) {
        const int r = idx >> 5, c16 = idx & 31;
        const float4 x = *((const float4*)(src + (size_t)r * 128) + c16);
        const __nv_bfloat16 h0 = __float2bfloat16_rn(x.x);
        const __nv_bfloat16 h1 = __float2bfloat16_rn(x.y);
        const __nv_bfloat16 h2 = __float2bfloat16_rn(x.z);
        const __nv_bfloat16 h3 = __float2bfloat16_rn(x.w);
        const __nv_bfloat16 l0 = __float2bfloat16_rn(x.x - __bfloat162float(h0));
        const __nv_bfloat16 l1 = __float2bfloat16_rn(x.y - __bfloat162float(h1));
        const __nv_bfloat16 l2 = __float2bfloat16_rn(x.z - __bfloat162float(h2));
        const __nv_bfloat16 l3 = __float2bfloat16_rn(x.w - __bfloat162float(h3));
        uint2 hp, lp;
        hp.x = (u32)__bfloat16_as_ushort(h0) | ((u32)__bfloat16_as_ushort(h1) << 16);
        hp.y = (u32)__bfloat16_as_ushort(h2) | ((u32)__bfloat16_as_ushort(h3) << 16);
        lp.x = (u32)__bfloat16_as_ushort(l0) | ((u32)__bfloat16_as_ushort(l1) << 16);
        lp.y = (u32)__bfloat16_as_ushort(l2) | ((u32)__bfloat16_as_ushort(l3) << 16);
        *(uint2*)(bufp + r * 272 + c16 * 8)       = hp;
        *(uint2*)(bufp + IMG + r * 272 + c16 * 8) = lp;
    }
}

__global__ void __launch_bounds__(256) k_hmma(const float* __restrict__ mem,
                                              const float* __restrict__ v)
{
    extern __shared__ char sm[];
    const int tid = threadIdx.x, w = tid >> 5, lane = tid & 31;
    const u32 smb = smem_u32(sm);
    const int G0 = blockIdx.x * 24;
    const int Gend = min(G0 + 24, NGRP);
    const int T = (Gend - G0 + 5) / 6;
    const int b0 = G0 >> 9;

    {   // A^T images -> smem
        const uint4* src = (const uint4*)g_ATsw;
        uint4* dst = (uint4*)(sm + AT_OFF);
        for (int k = tid; k < BUFSZ / 16; k += 256) dst[k] = src[k];
    }
    for (int idx = tid; idx < 20 * 128; idx += 256) {
        const int n = idx >> 7, e = idx & 127;
        ((float*)(sm + KB_OFF))[n * 132 + e] = g_kb[n * 128 + e];
    }
    if (tid < 128) {
        ((float*)(sm + QC_OFF))[tid]       = g_qc[b0 * 128 + tid];
        ((float*)(sm + QC_OFF))[128 + tid] = g_qc[min(b0 + 1, Bz - 1) * 128 + tid];
        ((float*)(sm + SV_OFF))[tid]       = v[tid];
    }
    load_tile(sm, mem, G0, min(6, Gend - G0), 0, tid);
    __syncthreads();

    float* aln = (float*)(sm + ALN_OFF);
    float* spb = (float*)(sm + SPB_OFF);
    const float* kbs = (const float*)(sm + KB_OFF);
    const float* qcs = (const float*)(sm + QC_OFF);
    const float* sv  = (const float*)(sm + SV_OFF);

    // lane-invariant fragment address components
    const u32 arow = (lane & 7) + ((lane >> 3) & 1) * 8;
    const u32 acol = (lane >> 4) * 16;
    const u32 brow = (lane & 7) + ((lane >> 4) & 1) * 8;
    const u32 bcol = ((lane >> 3) & 1) * 16;
    const u32 abase0 = smb + (w * 16 + arow) * 272 + acol;
    const u32 bbase  = smb + AT_OFF + brow * 272 + bcol;

    for (int t = 0; t < T; t++) {
        if (t + 1 < T)
            load_tile(sm, mem, G0 + 6 * (t + 1), min(6, Gend - (G0 + 6 * (t + 1))), (t + 1) & 1, tid);

        // ---- mma for tile t ----
        float acc[16][4];
#pragma unroll
        for (int nt = 0; nt < 16; nt++) { acc[nt][0] = acc[nt][1] = acc[nt][2] = acc[nt][3] = 0.f; }
        const u32 abase = abase0 + (t & 1) * BUFSZ;
#pragma unroll
        for (int k = 0; k < 8; k++) {
            u32 ahi[4], alo[4];
            const u32 aaddr = abase + k * 32;
            ldsm4(ahi, aaddr);
            ldsm4(alo, aaddr + IMG);
#pragma unroll
            for (int p = 0; p < 8; p++) {
                u32 bhi[4], blo[4];
                const u32 baddr = bbase + p * (16 * 272) + k * 32;
                ldsm4(bhi, baddr);
                ldsm4(blo, baddr + IMG);
                mma16816(acc[2 * p],     ahi, bhi[0], bhi[1]);
                mma16816(acc[2 * p],     ahi, blo[0], blo[1]);
                mma16816(acc[2 * p],     alo, bhi[0], bhi[1]);
                mma16816(acc[2 * p + 1], ahi, bhi[2], bhi[3]);
                mma16816(acc[2 * p + 1], ahi, blo[2], blo[3]);
                mma16816(acc[2 * p + 1], alo, bhi[2], bhi[3]);
            }
        }

        // ---- epilogue: tanh + v-weighted row sums ----
        const int Gt0 = G0 + 6 * t;
        const int ng = min(6, Gend - Gt0);
        const int rows = ng * 20;
        const int rA = (w << 4) + (lane >> 2);
        const int rB = rA + 8;
        const int gA = min(rA / 20, ng - 1), gB = min(rB / 20, ng - 1);
        const int nA = rA % 20, nB2 = rB % 20;
        const float* qA = qcs + (((Gt0 + gA) >> 9) - b0) * 128;
        const float* qB = qcs + (((Gt0 + gB) >> 9) - b0) * 128;
        const float* kA = kbs + nA * 132;
        const float* kB = kbs + nB2 * 132;
        const int cb = 2 * (lane & 3);
        float sumA = 0.f, sumB = 0.f;
#pragma unroll
        for (int nt = 0; nt < 16; nt++) {
            const int c0 = nt * 8 + cb;
            const float2 ka = *(const float2*)(kA + c0);
            const float2 kb2 = *(const float2*)(kB + c0);
            const float2 qa = *(const float2*)(qA + c0);
            const float2 qb = *(const float2*)(qB + c0);
            const float2 vv = *(const float2*)(sv + c0);
            sumA += vv.x * tanh_fast(acc[nt][0] + ka.x + qa.x);
            sumA += vv.y * tanh_fast(acc[nt][1] + ka.y + qa.y);
            sumB += vv.x * tanh_fast(acc[nt][2] + kb2.x + qb.x);
            sumB += vv.y * tanh_fast(acc[nt][3] + kb2.y + qb.y);
        }
        sumA += __shfl_xor_sync(0xffffffffu, sumA, 1);
        sumA += __shfl_xor_sync(0xffffffffu, sumA, 2);
        sumB += __shfl_xor_sync(0xffffffffu, sumB, 1);
        sumB += __shfl_xor_sync(0xffffffffu, sumB, 2);
        if ((lane & 3) == 0) { aln[rA] = sumA; aln[rB] = sumB; }
        __syncthreads();

        if (tid < rows) {
            const int gb = (tid / 20) * 20;
            float mx = -1e30f;
#pragma unroll
            for (int n2 = 0; n2 < 20; n2++) mx = fmaxf(mx, aln[gb + n2]);
            float Z = 0.f;
#pragma unroll
            for (int n2 = 0; n2 < 20; n2++) Z += __expf(aln[gb + n2] - mx);
            spb[tid] = __expf(aln[tid] - mx) / Z;
        }
        __syncthreads();

        {   // tm readback from hi+lo smem
            const char* bufp = sm + (t & 1) * BUFSZ;
            const int e = tid & 127, gh = tid >> 7;
#pragma unroll
            for (int g2 = 0; g2 < 3; g2++) {
                const int g = gh * 3 + g2;
                if (g < ng) {
                    float accv = 0.f;
                    const int r0 = g * 20;
#pragma unroll
                    for (int n2 = 0; n2 < 20; n2++) {
                        const int r = r0 + n2;
                        const u32 h = *(const unsigned short*)(bufp + r * 272 + e * 2);
                        const u32 l = *(const unsigned short*)(bufp + IMG + r * 272 + e * 2);
                        accv += spb[r] * (__uint_as_float(h << 16) + __uint_as_float(l << 16));
                    }
                    g_tm[(size_t)(Gt0 + g) * 128 + e] = accv;
                }
            }
        }
        __syncthreads();
    }
}

// ============================================================
#define ST 16
__global__ void __launch_bounds__(128) k_align2(
    const float* __restrict__ stories, const float* __restrict__ w)
{
    const int b = blockIdx.y, s0 = blockIdx.x * ST;
    const int tid = threadIdx.x, lane = tid & 31, wid = tid >> 5;
    __shared__ u64 sp[EMB * ST];
    __shared__ float s_part[4 * ST];
#pragma unroll
    for (int si = 0; si < ST; si++) {
        const size_t base = ((size_t)(b * Sz + s0 + si)) * EMB + tid;
        sp[tid * ST + si] = pack2(g_tm[base], stories[base]);
    }
    __syncthreads();
    u64 acc[ST];
#pragma unroll
    for (int si = 0; si < ST; si++) acc[si] = 0ull;
#pragma unroll 2
    for (int e = 0; e < EMB; e++) {
        const u64 de = g_DE[e * INNER + tid];
        const ulonglong2* row = (const ulonglong2*)(sp + e * ST);
#pragma unroll
        for (int k = 0; k < ST / 2; k++) {
            const ulonglong2 m = row[k];
            ffma2(acc[2 * k],     m.x, de);
            ffma2(acc[2 * k + 1], m.y, de);
        }
    }
    const float tfi = g_tfv[b * INNER + tid];
    const float wi  = w[tid];
    float tv[ST];
#pragma unroll
    for (int si = 0; si < ST; si++) {
        const float2 f = unpack2(acc[si]);
        float t = wi * tanh_fast(f.x + f.y + tfi);
#pragma unroll
        for (int o = 16; o > 0; o >>= 1) t += __shfl_xor_sync(0xffffffffu, t, o);
        tv[si] = t;
    }
    if (lane == 0) {
#pragma unroll
        for (int si = 0; si < ST; si++) s_part[wid * ST + si] = tv[si];
    }
    __syncthreads();
    if (tid < ST)
        g_talign[b * Sz + s0 + tid] =
            s_part[tid] + s_part[ST + tid] + s_part[2 * ST + tid] + s_part[3 * ST + tid];
}

__global__ void __launch_bounds__(128) k_temporal(const float* __restrict__ mask)
{
    const int b = blockIdx.x, tid = threadIdx.x, lane = tid & 31, wid = tid >> 5;
    __shared__ float sp[Sz];
    __shared__ float sr[4];
    float vals[4];
    float mx = neg_inf_f();
#pragma unroll
    for (int r = 0; r < 4; r++) {
        const int s = r * 128 + tid;
        const float ta = g_talign[b * Sz + s];
        const float m  = mask[b * Sz + s];
        const float ml = (m != 0.f) ? ta * m : neg_inf_f();
        vals[r] = ml;
        mx = fmaxf(mx, ml);
    }
#pragma unroll
    for (int o = 16; o > 0; o >>= 1) mx = fmaxf(mx, __shfl_xor_sync(0xffffffffu, mx, o));
    if (lane == 0) sr[wid] = mx;
    __syncthreads();
    mx = fmaxf(fmaxf(sr[0], sr[1]), fmaxf(sr[2], sr[3]));
    __syncthreads();
    float Z = 0.f;
#pragma unroll
    for (int r = 0; r < 4; r++) {
        const float ev = __expf(vals[r] - mx);
        sp[r * 128 + tid] = ev;
        Z += ev;
    }
#pragma unroll
    for (int o = 16; o > 0; o >>= 1) Z += __shfl_xor_sync(0xffffffffu, Z, o);
    if (lane == 0) sr[wid] = Z;
    __syncthreads();
    Z = sr[0] + sr[1] + sr[2] + sr[3];
    const float invZ = 1.f / Z;
    float o_ = 0.f;
    const float* tmb = g_tm + (size_t)b * Sz * EMB + tid;
#pragma unroll 8
    for (int s = 0; s < Sz; s++) o_ += sp[s] * tmb[(size_t)s * EMB];
    g_ob[b * EMB + tid] = o_ * invZ + g_uH[b * EMB + tid];
}

__global__ void __launch_bounds__(128) k_logits(const float* __restrict__ R,
                                                float* __restrict__ out)
{
    __shared__ u64 so2[EMB * (Bz / 2)];
    const int tid = threadIdx.x;
#pragma unroll
    for (int r = 0; r < EMB * (Bz / 2) / 128; r++) {
        const int idx = r * 128 + tid;
        const int e = idx >> 4, bb = idx & 15;
        so2[idx] = pack2(g_ob[(2 * bb) * EMB + e], g_ob[(2 * bb + 1) * EMB + e]);
    }
    __syncthreads();
    const int col = blockIdx.x * 128 + tid;
    if (col >= VOCAB) return;
    u64 acc[Bz / 2];
#pragma unroll
    for (int j = 0; j < Bz / 2; j++) acc[j] = 0ull;
#pragma unroll 2
    for (int e = 0; e < EMB; e++) {
        const u64 rd = dup2(R[(size_t)e * VOCAB + col]);
        const u64* row = so2 + e * (Bz / 2);
#pragma unroll
        for (int bb = 0; bb < Bz / 2; bb++) ffma2(acc[bb], rd, row[bb]);
    }
#pragma unroll
    for (int bb = 0; bb < Bz / 2; bb++) {
        const float2 f = unpack2(acc[bb]);
        out[(size_t)(2 * bb) * VOCAB + col]     = f.x;
        out[(size_t)(2 * bb + 1) * VOCAB + col] = f.y;
    }
}

// ============================================================
extern "C" void kernel_launch(void* const* d_in, const int* in_sizes, int n_in,
                              void* d_out, int out_size)
{
    const float* memories = (const float*)d_in[0];
    const float* stories  = (const float*)d_in[1];
    const float* smask    = (const float*)d_in[2];
    const int*   queries  = (const int*)  d_in[3];
    const int*   keys     = (const int*)  d_in[4];
    const float* emb      = (const float*)d_in[5];
    const float* mmask    = (const float*)d_in[6];
    const float* A        = (const float*)d_in[7];
    const float* Bm       = (const float*)d_in[8];
    const float* C        = (const float*)d_in[9];
    const float* v        = (const float*)d_in[10];
    const float* D        = (const float*)d_in[11];
    const float* E        = (const float*)d_in[12];
    const float* F        = (const float*)d_in[13];
    const float* w        = (const float*)d_in[14];
    const float* H        = (const float*)d_in[15];
    const float* R        = (const float*)d_in[16];
    float* out = (float*)d_out;

    cudaFuncSetAttribute(k_hmma, cudaFuncAttributeMaxDynamicSharedMemorySize, DYN_SMEM);

    k_prep<<<Bz, 128>>>(queries, emb, mmask, C, F, H);
    k_kb<<<NB, 128>>>(keys, emb, Bm);
    k_de<<<EMB * INNER / 128, 128>>>(D, E);
    k_split<<<EMB * INNER / 128, 128>>>(A);
    k_hmma<<<(NGRP + 23) / 24, 256, DYN_SMEM>>>(memories, v);
    k_align2<<<dim3(Sz / ST, Bz), 128>>>(stories, w);
    k_temporal<<<Bz, 128>>>(smask);
    k_logits<<<(VOCAB + 127) / 128, 128>>>(R, out);
}

// round 5
// speedup vs baseline: 1.6954x; 1.1807x over previous
#include <cuda_runtime.h>
#include <cuda_bf16.h>
#include <math.h>
#include <stdint.h>

#define Bz 32
#define Sz 512
#define NB 20
#define EMB 128
#define INNER 128
#define VOCAB 40000
#define QL 20
#define NGRP (Bz * Sz)
#define NTILES 2731            // ceil(16384 / 6)

typedef unsigned long long u64;
typedef unsigned int u32;

// ---- packed f32x2 helpers ----
__device__ __forceinline__ u64 dup2(float a) {
    u64 r; asm("mov.b64 %0, {%1, %1};" : "=l"(r) : "f"(a)); return r;
}
__device__ __forceinline__ u64 pack2(float x, float y) {
    u64 r; asm("mov.b64 %0, {%1, %2};" : "=l"(r) : "f"(x), "f"(y)); return r;
}
__device__ __forceinline__ float2 unpack2(u64 v) {
    float2 f; asm("mov.b64 {%0, %1}, %2;" : "=f"(f.x), "=f"(f.y) : "l"(v)); return f;
}
__device__ __forceinline__ void ffma2(u64& d, u64 a, u64 b) {
    asm("fma.rn.f32x2 %0, %1, %2, %0;" : "+l"(d) : "l"(a), "l"(b));
}
__device__ __forceinline__ float neg_inf_f() { return __int_as_float(0xff800000); }
__device__ __forceinline__ float tanh_fast(float x) {
    float e = __expf(2.f * x);
    return 1.f - __fdividef(2.f, e + 1.f);
}

// ---- scratch ----
__device__ float g_qc[Bz * INNER];
__device__ float g_tfv[Bz * INNER];
__device__ float g_uH[Bz * EMB];
__device__ float g_kb[NB * INNER];
__device__ u64   g_DE[EMB * INNER];
__device__ float g_tm[Bz * Sz * EMB];
__device__ float g_talign[Bz * Sz];
__device__ float g_ob[Bz * EMB];
__device__ unsigned char g_ATsw[69632];   // A^T bf16 hi/lo images, 272B row stride

// ---- warp mma helpers ----
__device__ __forceinline__ u32 smem_u32(const void* p) {
    u32 a; asm("{ .reg .u64 t; cvta.to.shared.u64 t, %1; cvt.u32.u64 %0, t; }" : "=r"(a) : "l"(p));
    return a;
}
__device__ __forceinline__ void ldsm4(u32* r, u32 addr) {
    asm volatile("ldmatrix.sync.aligned.m8n8.x4.shared.b16 {%0,%1,%2,%3}, [%4];"
        : "=r"(r[0]), "=r"(r[1]), "=r"(r[2]), "=r"(r[3]) : "r"(addr));
}
__device__ __forceinline__ void mma16816(float* d, const u32* a, u32 b0, u32 b1) {
    asm volatile("mma.sync.aligned.m16n8k16.row.col.f32.bf16.bf16.f32 "
        "{%0,%1,%2,%3}, {%4,%5,%6,%7}, {%8,%9}, {%0,%1,%2,%3};"
        : "+f"(d[0]), "+f"(d[1]), "+f"(d[2]), "+f"(d[3])
        : "r"(a[0]), "r"(a[1]), "r"(a[2]), "r"(a[3]), "r"(b0), "r"(b1));
}

// named barriers (count = all 384 threads for FULL/EMPTY, 256 for consumer-only)
#define BAR_SYNC(id, n)   asm volatile("bar.sync %0, %1;"   :: "r"(id), "r"(n) : "memory")
#define BAR_ARRIVE(id, n) asm volatile("bar.arrive %0, %1;" :: "r"(id), "r"(n) : "memory")

// smem layout (bytes)
#define IMG    34816            // one 128x136 bf16 image
#define BUFSZ  69632            // hi + lo image
#define AT_OFF 139264           // A^T hi (lo at +IMG)
#define KB_OFF 208896           // kb [20][132] f32
#define SV_OFF 220480           // v  [128] f32
#define ALN_OFF 220992          // per-row align [128]
#define SPB_OFF 221504          // per-row softmax prob [128]
#define DYN_SMEM 222016

// ============================================================
// k_setup: prep(32) | kb(20) | de(128) | split(128) via blockIdx dispatch
// ============================================================
__global__ void __launch_bounds__(128) k_setup(
    const int* __restrict__ queries, const int* __restrict__ keys,
    const float* __restrict__ emb, const float* __restrict__ mmask,
    const float* __restrict__ C, const float* __restrict__ F,
    const float* __restrict__ H, const float* __restrict__ Bm,
    const float* __restrict__ D, const float* __restrict__ E,
    const float* __restrict__ A)
{
    const int blk = blockIdx.x, tid = threadIdx.x;
    if (blk < 32) {                       // prep
        const int b = blk;
        __shared__ float su[EMB];
        float u = 0.f;
#pragma unroll
        for (int q = 0; q < QL; q++)
            u += emb[(size_t)queries[b * QL + q] * EMB + tid] * mmask[q * EMB + tid];
        su[tid] = u;
        __syncthreads();
        float c = 0.f, f = 0.f, h = 0.f;
#pragma unroll 4
        for (int e = 0; e < EMB; e++) {
            const float ue = su[e];
            c += ue * C[e * INNER + tid];
            f += ue * F[e * INNER + tid];
            h += ue * H[e * EMB + tid];
        }
        g_qc[b * INNER + tid]  = c;
        g_tfv[b * INNER + tid] = f;
        g_uH[b * EMB + tid]    = h;
    } else if (blk < 52) {                // kb
        const int n = blk - 32;
        __shared__ float se[EMB];
        se[tid] = emb[(size_t)keys[n] * EMB + tid];
        __syncthreads();
        float a = 0.f;
#pragma unroll 4
        for (int e = 0; e < EMB; e++) a += se[e] * Bm[e * INNER + tid];
        g_kb[n * INNER + tid] = a;
    } else if (blk < 180) {               // de interleave
        const int i = (blk - 52) * 128 + tid;
        g_DE[i] = pack2(D[i], E[i]);
    } else {                              // split A -> A^T hi/lo images
        const int idx = (blk - 180) * 128 + tid;
        const int e = idx >> 7, i = idx & 127;
        const float x = A[e * 128 + i];
        const __nv_bfloat16 h = __float2bfloat16_rn(x);
        const __nv_bfloat16 l = __float2bfloat16_rn(x - __bfloat162float(h));
        *(unsigned short*)(g_ATsw + i * 272 + e * 2)       = __bfloat16_as_ushort(h);
        *(unsigned short*)(g_ATsw + IMG + i * 272 + e * 2) = __bfloat16_as_ushort(l);
    }
}

// ============================================================
// k_hmma: persistent, warp-specialized (8 mma warps + 4 load warps)
// ============================================================
__device__ __forceinline__ void load_tile(char* sm, const float* __restrict__ mem,
                                          int Gt0, int ng, int buf, int ptid)
{
    char* bufp = sm + buf * BUFSZ;
    const float* src = mem + (size_t)Gt0 * (NB * EMB);
    const int iters = ng * 20 * 32;
#pragma unroll 2
    for (int idx = ptid; idx < iters; idx += 128) {
        const int r = idx >> 5, c16 = idx & 31;
        const float4 x = *((const float4*)(src + (size_t)r * 128) + c16);
        const __nv_bfloat16 h0 = __float2bfloat16_rn(x.x);
        const __nv_bfloat16 h1 = __float2bfloat16_rn(x.y);
        const __nv_bfloat16 h2 = __float2bfloat16_rn(x.z);
        const __nv_bfloat16 h3 = __float2bfloat16_rn(x.w);
        const __nv_bfloat16 l0 = __float2bfloat16_rn(x.x - __bfloat162float(h0));
        const __nv_bfloat16 l1 = __float2bfloat16_rn(x.y - __bfloat162float(h1));
        const __nv_bfloat16 l2 = __float2bfloat16_rn(x.z - __bfloat162float(h2));
        const __nv_bfloat16 l3 = __float2bfloat16_rn(x.w - __bfloat162float(h3));
        uint2 hp, lp;
        hp.x = (u32)__bfloat16_as_ushort(h0) | ((u32)__bfloat16_as_ushort(h1) << 16);
        hp.y = (u32)__bfloat16_as_ushort(h2) | ((u32)__bfloat16_as_ushort(h3) << 16);
        lp.x = (u32)__bfloat16_as_ushort(l0) | ((u32)__bfloat16_as_ushort(l1) << 16);
        lp.y = (u32)__bfloat16_as_ushort(l2) | ((u32)__bfloat16_as_ushort(l3) << 16);
        *(uint2*)(bufp + r * 272 + c16 * 8)       = hp;
        *(uint2*)(bufp + IMG + r * 272 + c16 * 8) = lp;
    }
}

__global__ void __launch_bounds__(384, 1) k_hmma(const float* __restrict__ mem,
                                                 const float* __restrict__ v)
{
    extern __shared__ char sm[];
    const int tid = threadIdx.x, w = tid >> 5, lane = tid & 31;
    const u32 smb = smem_u32(sm);

    {   // A^T images -> smem (once per persistent CTA)
        const uint4* src = (const uint4*)g_ATsw;
        uint4* dst = (uint4*)(sm + AT_OFF);
        for (int k = tid; k < BUFSZ / 16; k += 384) dst[k] = src[k];
    }
    for (int idx = tid; idx < 20 * 128; idx += 384) {
        const int n = idx >> 7, e = idx & 127;
        ((float*)(sm + KB_OFF))[n * 132 + e] = g_kb[n * 128 + e];
    }
    if (tid < 128) ((float*)(sm + SV_OFF))[tid] = v[tid];
    __syncthreads();

    if (w >= 8) {
        // ---------------- producer warps ----------------
        const int ptid = tid - 256;
        int lt = 0;
        for (int tt = blockIdx.x; tt < NTILES; tt += gridDim.x, lt++) {
            if (lt >= 2) BAR_SYNC(3 + (lt & 1), 384);
            const int Gt0 = tt * 6;
            const int ng = min(6, NGRP - Gt0);
            load_tile(sm, mem, Gt0, ng, lt & 1, ptid);
            BAR_ARRIVE(1 + (lt & 1), 384);
        }
        return;
    }

    // ---------------- consumer warps (w 0..7, tid 0..255) ----------------
    float* aln = (float*)(sm + ALN_OFF);
    float* spb = (float*)(sm + SPB_OFF);
    const float* kbs = (const float*)(sm + KB_OFF);
    const float* sv  = (const float*)(sm + SV_OFF);

    const u32 arow = (lane & 7) + ((lane >> 3) & 1) * 8;
    const u32 acol = (lane >> 4) * 16;
    const u32 brow = (lane & 7) + ((lane >> 4) & 1) * 8;
    const u32 bcol = ((lane >> 3) & 1) * 16;
    const u32 abase0 = smb + (w * 16 + arow) * 272 + acol;
    const u32 bbase  = smb + AT_OFF + brow * 272 + bcol;

    int lt = 0;
    for (int tt = blockIdx.x; tt < NTILES; tt += gridDim.x, lt++) {
        BAR_SYNC(1 + (lt & 1), 384);

        // ---- mma ----
        float acc[16][4];
#pragma unroll
        for (int nt = 0; nt < 16; nt++) { acc[nt][0] = acc[nt][1] = acc[nt][2] = acc[nt][3] = 0.f; }
        const u32 abase = abase0 + (lt & 1) * BUFSZ;
#pragma unroll
        for (int k = 0; k < 8; k++) {
            u32 ahi[4], alo[4];
            const u32 aaddr = abase + k * 32;
            ldsm4(ahi, aaddr);
            ldsm4(alo, aaddr + IMG);
#pragma unroll
            for (int p = 0; p < 8; p++) {
                u32 bhi[4], blo[4];
                const u32 baddr = bbase + p * (16 * 272) + k * 32;
                ldsm4(bhi, baddr);
                ldsm4(blo, baddr + IMG);
                mma16816(acc[2 * p],     ahi, bhi[0], bhi[1]);
                mma16816(acc[2 * p],     ahi, blo[0], blo[1]);
                mma16816(acc[2 * p],     alo, bhi[0], bhi[1]);
                mma16816(acc[2 * p + 1], ahi, bhi[2], bhi[3]);
                mma16816(acc[2 * p + 1], ahi, blo[2], blo[3]);
                mma16816(acc[2 * p + 1], alo, bhi[2], bhi[3]);
            }
        }

        // ---- epilogue ----
        const int Gt0 = tt * 6;
        const int ng = min(6, NGRP - Gt0);
        const int rows = ng * 20;
        const int rA = (w << 4) + (lane >> 2);
        const int rB = rA + 8;
        const int gA = min(rA / 20, ng - 1), gB = min(rB / 20, ng - 1);
        const int nA = rA % 20, nB2 = rB % 20;
        const float* qA = g_qc + (size_t)((Gt0 + gA) >> 9) * 128;
        const float* qB = g_qc + (size_t)((Gt0 + gB) >> 9) * 128;
        const float* kA = kbs + nA * 132;
        const float* kB = kbs + nB2 * 132;
        const int cb = 2 * (lane & 3);
        float sumA = 0.f, sumB = 0.f;
#pragma unroll
        for (int nt = 0; nt < 16; nt++) {
            const int c0 = nt * 8 + cb;
            const float2 ka  = *(const float2*)(kA + c0);
            const float2 kb2 = *(const float2*)(kB + c0);
            const float2 qa  = *(const float2*)(qA + c0);
            const float2 qb  = *(const float2*)(qB + c0);
            const float2 vv  = *(const float2*)(sv + c0);
            sumA += vv.x * tanh_fast(acc[nt][0] + ka.x + qa.x);
            sumA += vv.y * tanh_fast(acc[nt][1] + ka.y + qa.y);
            sumB += vv.x * tanh_fast(acc[nt][2] + kb2.x + qb.x);
            sumB += vv.y * tanh_fast(acc[nt][3] + kb2.y + qb.y);
        }
        sumA += __shfl_xor_sync(0xffffffffu, sumA, 1);
        sumA += __shfl_xor_sync(0xffffffffu, sumA, 2);
        sumB += __shfl_xor_sync(0xffffffffu, sumB, 1);
        sumB += __shfl_xor_sync(0xffffffffu, sumB, 2);
        if ((lane & 3) == 0) { aln[rA] = sumA; aln[rB] = sumB; }
        BAR_SYNC(5, 256);

        if (tid < rows) {
            const int gb = (tid / 20) * 20;
            float mx = -1e30f;
#pragma unroll
            for (int n2 = 0; n2 < 20; n2++) mx = fmaxf(mx, aln[gb + n2]);
            float Z = 0.f;
#pragma unroll
            for (int n2 = 0; n2 < 20; n2++) Z += __expf(aln[gb + n2] - mx);
            spb[tid] = __expf(aln[tid] - mx) / Z;
        }
        BAR_SYNC(5, 256);

        {   // tm readback from hi+lo smem
            const char* bufp = sm + (lt & 1) * BUFSZ;
            const int e = tid & 127, gh = tid >> 7;
#pragma unroll
            for (int g2 = 0; g2 < 3; g2++) {
                const int g = gh * 3 + g2;
                if (g < ng) {
                    float accv = 0.f;
                    const int r0 = g * 20;
#pragma unroll
                    for (int n2 = 0; n2 < 20; n2++) {
                        const int r = r0 + n2;
                        const u32 h = *(const unsigned short*)(bufp + r * 272 + e * 2);
                        const u32 l = *(const unsigned short*)(bufp + IMG + r * 272 + e * 2);
                        accv += spb[r] * (__uint_as_float(h << 16) + __uint_as_float(l << 16));
                    }
                    g_tm[(size_t)(Gt0 + g) * 128 + e] = accv;
                }
            }
        }
        BAR_ARRIVE(3 + (lt & 1), 384);
    }
}

// ============================================================
#define ST 16
__global__ void __launch_bounds__(128) k_align2(
    const float* __restrict__ stories, const float* __restrict__ w)
{
    const int b = blockIdx.y, s0 = blockIdx.x * ST;
    const int tid = threadIdx.x, lane = tid & 31, wid = tid >> 5;
    __shared__ u64 sp[EMB * ST];
    __shared__ float s_part[4 * ST];
#pragma unroll
    for (int si = 0; si < ST; si++) {
        const size_t base = ((size_t)(b * Sz + s0 + si)) * EMB + tid;
        sp[tid * ST + si] = pack2(g_tm[base], stories[base]);
    }
    __syncthreads();
    u64 acc[ST];
#pragma unroll
    for (int si = 0; si < ST; si++) acc[si] = 0ull;
#pragma unroll 2
    for (int e = 0; e < EMB; e++) {
        const u64 de = g_DE[e * INNER + tid];
        const ulonglong2* row = (const ulonglong2*)(sp + e * ST);
#pragma unroll
        for (int k = 0; k < ST / 2; k++) {
            const ulonglong2 m = row[k];
            ffma2(acc[2 * k],     m.x, de);
            ffma2(acc[2 * k + 1], m.y, de);
        }
    }
    const float tfi = g_tfv[b * INNER + tid];
    const float wi  = w[tid];
    float tv[ST];
#pragma unroll
    for (int si = 0; si < ST; si++) {
        const float2 f = unpack2(acc[si]);
        float t = wi * tanh_fast(f.x + f.y + tfi);
#pragma unroll
        for (int o = 16; o > 0; o >>= 1) t += __shfl_xor_sync(0xffffffffu, t, o);
        tv[si] = t;
    }
    if (lane == 0) {
#pragma unroll
        for (int si = 0; si < ST; si++) s_part[wid * ST + si] = tv[si];
    }
    __syncthreads();
    if (tid < ST)
        g_talign[b * Sz + s0 + tid] =
            s_part[tid] + s_part[ST + tid] + s_part[2 * ST + tid] + s_part[3 * ST + tid];
}

__global__ void __launch_bounds__(128) k_temporal(const float* __restrict__ mask)
{
    const int b = blockIdx.x, tid = threadIdx.x, lane = tid & 31, wid = tid >> 5;
    __shared__ float sp[Sz];
    __shared__ float sr[4];
    float vals[4];
    float mx = neg_inf_f();
#pragma unroll
    for (int r = 0; r < 4; r++) {
        const int s = r * 128 + tid;
        const float ta = g_talign[b * Sz + s];
        const float m  = mask[b * Sz + s];
        const float ml = (m != 0.f) ? ta * m : neg_inf_f();
        vals[r] = ml;
        mx = fmaxf(mx, ml);
    }
#pragma unroll
    for (int o = 16; o > 0; o >>= 1) mx = fmaxf(mx, __shfl_xor_sync(0xffffffffu, mx, o));
    if (lane == 0) sr[wid] = mx;
    __syncthreads();
    mx = fmaxf(fmaxf(sr[0], sr[1]), fmaxf(sr[2], sr[3]));
    __syncthreads();
    float Z = 0.f;
#pragma unroll
    for (int r = 0; r < 4; r++) {
        const float ev = __expf(vals[r] - mx);
        sp[r * 128 + tid] = ev;
        Z += ev;
    }
#pragma unroll
    for (int o = 16; o > 0; o >>= 1) Z += __shfl_xor_sync(0xffffffffu, Z, o);
    if (lane == 0) sr[wid] = Z;
    __syncthreads();
    Z = sr[0] + sr[1] + sr[2] + sr[3];
    const float invZ = 1.f / Z;
    float o_ = 0.f;
    const float* tmb = g_tm + (size_t)b * Sz * EMB + tid;
#pragma unroll 16
    for (int s = 0; s < Sz; s++) o_ += sp[s] * tmb[(size_t)s * EMB];
    g_ob[b * EMB + tid] = o_ * invZ + g_uH[b * EMB + tid];
}

__global__ void __launch_bounds__(128) k_logits(const float* __restrict__ R,
                                                float* __restrict__ out)
{
    __shared__ u64 so2[EMB * (Bz / 2)];
    const int tid = threadIdx.x;
#pragma unroll
    for (int r = 0; r < EMB * (Bz / 2) / 128; r++) {
        const int idx = r * 128 + tid;
        const int e = idx >> 4, bb = idx & 15;
        so2[idx] = pack2(g_ob[(2 * bb) * EMB + e], g_ob[(2 * bb + 1) * EMB + e]);
    }
    __syncthreads();
    const int col = blockIdx.x * 128 + tid;
    if (col >= VOCAB) return;
    u64 acc[Bz / 2];
#pragma unroll
    for (int j = 0; j < Bz / 2; j++) acc[j] = 0ull;
#pragma unroll 4
    for (int e = 0; e < EMB; e++) {
        const u64 rd = dup2(R[(size_t)e * VOCAB + col]);
        const u64* row = so2 + e * (Bz / 2);
#pragma unroll
        for (int bb = 0; bb < Bz / 2; bb++) ffma2(acc[bb], rd, row[bb]);
    }
#pragma unroll
    for (int bb = 0; bb < Bz / 2; bb++) {
        const float2 f = unpack2(acc[bb]);
        out[(size_t)(2 * bb) * VOCAB + col]     = f.x;
        out[(size_t)(2 * bb + 1) * VOCAB + col] = f.y;
    }
}

// ============================================================
extern "C" void kernel_launch(void* const* d_in, const int* in_sizes, int n_in,
                              void* d_out, int out_size)
{
    const float* memories = (const float*)d_in[0];
    const float* stories  = (const float*)d_in[1];
    const float* smask    = (const float*)d_in[2];
    const int*   queries  = (const int*)  d_in[3];
    const int*   keys     = (const int*)  d_in[4];
    const float* emb      = (const float*)d_in[5];
    const float* mmask    = (const float*)d_in[6];
    const float* A        = (const float*)d_in[7];
    const float* Bm       = (const float*)d_in[8];
    const float* C        = (const float*)d_in[9];
    const float* v        = (const float*)d_in[10];
    const float* D        = (const float*)d_in[11];
    const float* E        = (const float*)d_in[12];
    const float* F        = (const float*)d_in[13];
    const float* w        = (const float*)d_in[14];
    const float* H        = (const float*)d_in[15];
    const float* R        = (const float*)d_in[16];
    float* out = (float*)d_out;

    cudaFuncSetAttribute(k_hmma, cudaFuncAttributeMaxDynamicSharedMemorySize, DYN_SMEM);

    k_setup<<<308, 128>>>(queries, keys, emb, mmask, C, F, H, Bm, D, E, A);
    k_hmma<<<148, 384, DYN_SMEM>>>(memories, v);
    k_align2<<<dim3(Sz / ST, Bz), 128>>>(stories, w);
    k_temporal<<<Bz, 128>>>(smask);
    k_logits<<<(VOCAB + 127) / 128, 128>>>(R, out);
}

// round 6
// speedup vs baseline: 1.7746x; 1.0467x over previous
#include <cuda_runtime.h>
#include <cuda_bf16.h>
#include <math.h>
#include <stdint.h>

#define Bz 32
#define Sz 512
#define NB 20
#define EMB 128
#define INNER 128
#define VOCAB 40000
#define QL 20
#define NGRP (Bz * Sz)
#define NTILES 2731            // ceil(16384 / 6)

typedef unsigned long long u64;
typedef unsigned int u32;

// ---- packed f32x2 helpers ----
__device__ __forceinline__ u64 dup2(float a) {
    u64 r; asm("mov.b64 %0, {%1, %1};" : "=l"(r) : "f"(a)); return r;
}
__device__ __forceinline__ u64 pack2(float x, float y) {
    u64 r; asm("mov.b64 %0, {%1, %2};" : "=l"(r) : "f"(x), "f"(y)); return r;
}
__device__ __forceinline__ float2 unpack2(u64 v) {
    float2 f; asm("mov.b64 {%0, %1}, %2;" : "=f"(f.x), "=f"(f.y) : "l"(v)); return f;
}
__device__ __forceinline__ void ffma2(u64& d, u64 a, u64 b) {
    asm("fma.rn.f32x2 %0, %1, %2, %0;" : "+l"(d) : "l"(a), "l"(b));
}
__device__ __forceinline__ float neg_inf_f() { return __int_as_float(0xff800000); }
__device__ __forceinline__ float tanh_fast(float x) {
    float e = __expf(2.f * x);
    return 1.f - __fdividef(2.f, e + 1.f);
}

// ---- scratch ----
__device__ float g_qc[Bz * INNER];
__device__ float g_tfv[Bz * INNER];
__device__ float g_uH[Bz * EMB];
__device__ float g_kb[NB * INNER];
__device__ u64   g_DE[EMB * INNER];
__device__ float g_tm[Bz * Sz * EMB];
__device__ float g_talign[Bz * Sz];
__device__ float g_ob[Bz * EMB];
__device__ unsigned char g_ATsw[69632];   // A^T bf16 hi/lo images, 272B row stride

// ---- warp mma helpers ----
__device__ __forceinline__ u32 smem_u32(const void* p) {
    u32 a; asm("{ .reg .u64 t; cvta.to.shared.u64 t, %1; cvt.u32.u64 %0, t; }" : "=r"(a) : "l"(p));
    return a;
}
__device__ __forceinline__ void ldsm4(u32* r, u32 addr) {
    asm volatile("ldmatrix.sync.aligned.m8n8.x4.shared.b16 {%0,%1,%2,%3}, [%4];"
        : "=r"(r[0]), "=r"(r[1]), "=r"(r[2]), "=r"(r[3]) : "r"(addr));
}
__device__ __forceinline__ void mma16816(float* d, const u32* a, u32 b0, u32 b1) {
    asm volatile("mma.sync.aligned.m16n8k16.row.col.f32.bf16.bf16.f32 "
        "{%0,%1,%2,%3}, {%4,%5,%6,%7}, {%8,%9}, {%0,%1,%2,%3};"
        : "+f"(d[0]), "+f"(d[1]), "+f"(d[2]), "+f"(d[3])
        : "r"(a[0]), "r"(a[1]), "r"(a[2]), "r"(a[3]), "r"(b0), "r"(b1));
}

#define BAR_SYNC(id, n)   asm volatile("bar.sync %0, %1;"   :: "r"(id), "r"(n) : "memory")
#define BAR_ARRIVE(id, n) asm volatile("bar.arrive %0, %1;" :: "r"(id), "r"(n) : "memory")

// smem layout (bytes)
#define IMG    34816
#define BUFSZ  69632
#define AT_OFF 139264
#define KB_OFF 208896
#define SV_OFF 220480
#define ALN_OFF 220992
#define SPB_OFF 221504
#define DYN_SMEM 222016

// ============================================================
__global__ void __launch_bounds__(128) k_setup(
    const int* __restrict__ queries, const int* __restrict__ keys,
    const float* __restrict__ emb, const float* __restrict__ mmask,
    const float* __restrict__ C, const float* __restrict__ F,
    const float* __restrict__ H, const float* __restrict__ Bm,
    const float* __restrict__ D, const float* __restrict__ E,
    const float* __restrict__ A)
{
    const int blk = blockIdx.x, tid = threadIdx.x;
    if (blk < 32) {
        const int b = blk;
        __shared__ float su[EMB];
        float u = 0.f;
#pragma unroll
        for (int q = 0; q < QL; q++)
            u += emb[(size_t)queries[b * QL + q] * EMB + tid] * mmask[q * EMB + tid];
        su[tid] = u;
        __syncthreads();
        float c = 0.f, f = 0.f, h = 0.f;
#pragma unroll 4
        for (int e = 0; e < EMB; e++) {
            const float ue = su[e];
            c += ue * C[e * INNER + tid];
            f += ue * F[e * INNER + tid];
            h += ue * H[e * EMB + tid];
        }
        g_qc[b * INNER + tid]  = c;
        g_tfv[b * INNER + tid] = f;
        g_uH[b * EMB + tid]    = h;
    } else if (blk < 52) {
        const int n = blk - 32;
        __shared__ float se[EMB];
        se[tid] = emb[(size_t)keys[n] * EMB + tid];
        __syncthreads();
        float a = 0.f;
#pragma unroll 4
        for (int e = 0; e < EMB; e++) a += se[e] * Bm[e * INNER + tid];
        g_kb[n * INNER + tid] = a;
    } else if (blk < 180) {
        const int i = (blk - 52) * 128 + tid;
        g_DE[i] = pack2(D[i], E[i]);
    } else {
        const int idx = (blk - 180) * 128 + tid;
        const int e = idx >> 7, i = idx & 127;
        const float x = A[e * 128 + i];
        const __nv_bfloat16 h = __float2bfloat16_rn(x);
        const __nv_bfloat16 l = __float2bfloat16_rn(x - __bfloat162float(h));
        *(unsigned short*)(g_ATsw + i * 272 + e * 2)       = __bfloat16_as_ushort(h);
        *(unsigned short*)(g_ATsw + IMG + i * 272 + e * 2) = __bfloat16_as_ushort(l);
    }
}

// ============================================================
// k_hmma: persistent, warp-specialized, independent-chain MMA order
// ============================================================
__device__ __forceinline__ void load_tile(char* sm, const float* __restrict__ mem,
                                          int Gt0, int ng, int buf, int ptid)
{
    char* bufp = sm + buf * BUFSZ;
    const float* src = mem + (size_t)Gt0 * (NB * EMB);
    const int iters = ng * 20 * 32;
#pragma unroll 2
    for (int idx = ptid; idx < iters; idx += 128) {
        const int r = idx >> 5, c16 = idx & 31;
        const float4 x = *((const float4*)(src + (size_t)r * 128) + c16);
        const __nv_bfloat16 h0 = __float2bfloat16_rn(x.x);
        const __nv_bfloat16 h1 = __float2bfloat16_rn(x.y);
        const __nv_bfloat16 h2 = __float2bfloat16_rn(x.z);
        const __nv_bfloat16 h3 = __float2bfloat16_rn(x.w);
        const __nv_bfloat16 l0 = __float2bfloat16_rn(x.x - __bfloat162float(h0));
        const __nv_bfloat16 l1 = __float2bfloat16_rn(x.y - __bfloat162float(h1));
        const __nv_bfloat16 l2 = __float2bfloat16_rn(x.z - __bfloat162float(h2));
        const __nv_bfloat16 l3 = __float2bfloat16_rn(x.w - __bfloat162float(h3));
        uint2 hp, lp;
        hp.x = (u32)__bfloat16_as_ushort(h0) | ((u32)__bfloat16_as_ushort(h1) << 16);
        hp.y = (u32)__bfloat16_as_ushort(h2) | ((u32)__bfloat16_as_ushort(h3) << 16);
        lp.x = (u32)__bfloat16_as_ushort(l0) | ((u32)__bfloat16_as_ushort(l1) << 16);
        lp.y = (u32)__bfloat16_as_ushort(l2) | ((u32)__bfloat16_as_ushort(l3) << 16);
        *(uint2*)(bufp + r * 272 + c16 * 8)       = hp;
        *(uint2*)(bufp + IMG + r * 272 + c16 * 8) = lp;
    }
}

__global__ void __launch_bounds__(384, 1) k_hmma(const float* __restrict__ mem,
                                                 const float* __restrict__ v)
{
    extern __shared__ char sm[];
    const int tid = threadIdx.x, w = tid >> 5, lane = tid & 31;
    const u32 smb = smem_u32(sm);

    {
        const uint4* src = (const uint4*)g_ATsw;
        uint4* dst = (uint4*)(sm + AT_OFF);
        for (int k = tid; k < BUFSZ / 16; k += 384) dst[k] = src[k];
    }
    for (int idx = tid; idx < 20 * 128; idx += 384) {
        const int n = idx >> 7, e = idx & 127;
        ((float*)(sm + KB_OFF))[n * 132 + e] = g_kb[n * 128 + e];
    }
    if (tid < 128) ((float*)(sm + SV_OFF))[tid] = v[tid];
    __syncthreads();

    if (w >= 8) {
        // ---------------- producers ----------------
        const int ptid = tid - 256;
        int lt = 0;
        for (int tt = blockIdx.x; tt < NTILES; tt += gridDim.x, lt++) {
            if (lt >= 2) BAR_SYNC(3 + (lt & 1), 384);
            const int Gt0 = tt * 6;
            const int ng = min(6, NGRP - Gt0);
            load_tile(sm, mem, Gt0, ng, lt & 1, ptid);
            BAR_ARRIVE(1 + (lt & 1), 384);
        }
        return;
    }

    // ---------------- consumers ----------------
    float* aln = (float*)(sm + ALN_OFF);
    float* spb = (float*)(sm + SPB_OFF);
    const float* kbs = (const float*)(sm + KB_OFF);
    const float* sv  = (const float*)(sm + SV_OFF);

    const u32 arow = (lane & 7) + ((lane >> 3) & 1) * 8;
    const u32 acol = (lane >> 4) * 16;
    const u32 brow = (lane & 7) + ((lane >> 4) & 1) * 8;
    const u32 bcol = ((lane >> 3) & 1) * 16;
    const u32 abase0 = smb + (w * 16 + arow) * 272 + acol;
    const u32 bbase  = smb + AT_OFF + brow * 272 + bcol;

    int lt = 0;
    for (int tt = blockIdx.x; tt < NTILES; tt += gridDim.x, lt++) {
        BAR_SYNC(1 + (lt & 1), 384);

        // ---- mma: three independent-chain passes per k-step ----
        float acc[16][4];
#pragma unroll
        for (int nt = 0; nt < 16; nt++) { acc[nt][0] = acc[nt][1] = acc[nt][2] = acc[nt][3] = 0.f; }
        const u32 abase = abase0 + (lt & 1) * BUFSZ;
#pragma unroll
        for (int k = 0; k < 8; k++) {
            u32 ahi[4], alo[4], bhi[8][4];
            const u32 aaddr = abase + k * 32;
            ldsm4(ahi, aaddr);
            ldsm4(alo, aaddr + IMG);
            // pass 1: hh (16 independent accumulators)
#pragma unroll
            for (int p = 0; p < 8; p++) {
                ldsm4(bhi[p], bbase + p * (16 * 272) + k * 32);
                mma16816(acc[2 * p],     ahi, bhi[p][0], bhi[p][1]);
                mma16816(acc[2 * p + 1], ahi, bhi[p][2], bhi[p][3]);
            }
            // pass 2: lh (reuse bhi regs)
#pragma unroll
            for (int p = 0; p < 8; p++) {
                mma16816(acc[2 * p],     alo, bhi[p][0], bhi[p][1]);
                mma16816(acc[2 * p + 1], alo, bhi[p][2], bhi[p][3]);
            }
            // pass 3: hl
#pragma unroll
            for (int p = 0; p < 8; p++) {
                u32 blo[4];
                ldsm4(blo, bbase + p * (16 * 272) + k * 32 + IMG);
                mma16816(acc[2 * p],     ahi, blo[0], blo[1]);
                mma16816(acc[2 * p + 1], ahi, blo[2], blo[3]);
            }
        }

        // ---- epilogue ----
        const int Gt0 = tt * 6;
        const int ng = min(6, NGRP - Gt0);
        const int rows = ng * 20;
        const int rA = (w << 4) + (lane >> 2);
        const int rB = rA + 8;
        const int gA = min(rA / 20, ng - 1), gB = min(rB / 20, ng - 1);
        const int nA = rA % 20, nB2 = rB % 20;
        const float* qA = g_qc + (size_t)((Gt0 + gA) >> 9) * 128;
        const float* qB = g_qc + (size_t)((Gt0 + gB) >> 9) * 128;
        const float* kA = kbs + nA * 132;
        const float* kB = kbs + nB2 * 132;
        const int cb = 2 * (lane & 3);
        float sumA = 0.f, sumB = 0.f;
#pragma unroll
        for (int nt = 0; nt < 16; nt++) {
            const int c0 = nt * 8 + cb;
            const float2 ka  = *(const float2*)(kA + c0);
            const float2 kb2 = *(const float2*)(kB + c0);
            const float2 qa  = *(const float2*)(qA + c0);
            const float2 qb  = *(const float2*)(qB + c0);
            const float2 vv  = *(const float2*)(sv + c0);
            sumA += vv.x * tanh_fast(acc[nt][0] + ka.x + qa.x);
            sumA += vv.y * tanh_fast(acc[nt][1] + ka.y + qa.y);
            sumB += vv.x * tanh_fast(acc[nt][2] + kb2.x + qb.x);
            sumB += vv.y * tanh_fast(acc[nt][3] + kb2.y + qb.y);
        }
        sumA += __shfl_xor_sync(0xffffffffu, sumA, 1);
        sumA += __shfl_xor_sync(0xffffffffu, sumA, 2);
        sumB += __shfl_xor_sync(0xffffffffu, sumB, 1);
        sumB += __shfl_xor_sync(0xffffffffu, sumB, 2);
        if ((lane & 3) == 0) { aln[rA] = sumA; aln[rB] = sumB; }
        BAR_SYNC(5, 256);

        if (tid < rows) {
            const int gb = (tid / 20) * 20;
            float mx = -1e30f;
#pragma unroll
            for (int n2 = 0; n2 < 20; n2++) mx = fmaxf(mx, aln[gb + n2]);
            float Z = 0.f;
#pragma unroll
            for (int n2 = 0; n2 < 20; n2++) Z += __expf(aln[gb + n2] - mx);
            spb[tid] = __expf(aln[tid] - mx) / Z;
        }
        BAR_SYNC(5, 256);

        {   // tm readback from ORIGINAL fp32 memories (L1/L2-resident) — exact
            const float* msrc = mem + (size_t)Gt0 * (NB * EMB);
            const int e = tid & 127, gh = tid >> 7;
#pragma unroll
            for (int g2 = 0; g2 < 3; g2++) {
                const int g = gh * 3 + g2;
                if (g < ng) {
                    float accv = 0.f;
                    const int r0 = g * 20;
#pragma unroll
                    for (int n2 = 0; n2 < 20; n2++)
                        accv += spb[r0 + n2] * msrc[(size_t)(r0 + n2) * 128 + e];
                    g_tm[(size_t)(Gt0 + g) * 128 + e] = accv;
                }
            }
        }
        BAR_ARRIVE(3 + (lt & 1), 384);
    }
}

// ============================================================
#define ST 16
__global__ void __launch_bounds__(128) k_align2(
    const float* __restrict__ stories, const float* __restrict__ w)
{
    const int b = blockIdx.y, s0 = blockIdx.x * ST;
    const int tid = threadIdx.x, lane = tid & 31, wid = tid >> 5;
    __shared__ u64 sp[EMB * ST];
    __shared__ float s_part[4 * ST];
#pragma unroll
    for (int si = 0; si < ST; si++) {
        const size_t base = ((size_t)(b * Sz + s0 + si)) * EMB + tid;
        sp[tid * ST + si] = pack2(g_tm[base], stories[base]);
    }
    __syncthreads();
    u64 acc[ST];
#pragma unroll
    for (int si = 0; si < ST; si++) acc[si] = 0ull;
#pragma unroll 2
    for (int e = 0; e < EMB; e++) {
        const u64 de = g_DE[e * INNER + tid];
        const ulonglong2* row = (const ulonglong2*)(sp + e * ST);
#pragma unroll
        for (int k = 0; k < ST / 2; k++) {
            const ulonglong2 m = row[k];
            ffma2(acc[2 * k],     m.x, de);
            ffma2(acc[2 * k + 1], m.y, de);
        }
    }
    const float tfi = g_tfv[b * INNER + tid];
    const float wi  = w[tid];
    float tv[ST];
#pragma unroll
    for (int si = 0; si < ST; si++) {
        const float2 f = unpack2(acc[si]);
        float t = wi * tanh_fast(f.x + f.y + tfi);
#pragma unroll
        for (int o = 16; o > 0; o >>= 1) t += __shfl_xor_sync(0xffffffffu, t, o);
        tv[si] = t;
    }
    if (lane == 0) {
#pragma unroll
        for (int si = 0; si < ST; si++) s_part[wid * ST + si] = tv[si];
    }
    __syncthreads();
    if (tid < ST)
        g_talign[b * Sz + s0 + tid] =
            s_part[tid] + s_part[ST + tid] + s_part[2 * ST + tid] + s_part[3 * ST + tid];
}

// ============================================================
// k_temporal: grid (8 e-chunks, 32 b); each CTA owns 16 e-dims
// ============================================================
__global__ void __launch_bounds__(128) k_temporal(const float* __restrict__ mask)
{
    const int ec = blockIdx.x, b = blockIdx.y;
    const int tid = threadIdx.x, lane = tid & 31, wid = tid >> 5;
    __shared__ float sp[Sz];
    __shared__ float sr[4];
    __shared__ float s_part[8][16];

    float vals[4];
    float mx = neg_inf_f();
#pragma unroll
    for (int r = 0; r < 4; r++) {
        const int s = r * 128 + tid;
        const float ta = g_talign[b * Sz + s];
        const float m  = mask[b * Sz + s];
        const float ml = (m != 0.f) ? ta * m : neg_inf_f();
        vals[r] = ml;
        mx = fmaxf(mx, ml);
    }
#pragma unroll
    for (int o = 16; o > 0; o >>= 1) mx = fmaxf(mx, __shfl_xor_sync(0xffffffffu, mx, o));
    if (lane == 0) sr[wid] = mx;
    __syncthreads();
    mx = fmaxf(fmaxf(sr[0], sr[1]), fmaxf(sr[2], sr[3]));
    __syncthreads();
    float Z = 0.f;
#pragma unroll
    for (int r = 0; r < 4; r++) {
        const float ev = __expf(vals[r] - mx);
        sp[r * 128 + tid] = ev;
        Z += ev;
    }
#pragma unroll
    for (int o = 16; o > 0; o >>= 1) Z += __shfl_xor_sync(0xffffffffu, Z, o);
    if (lane == 0) sr[wid] = Z;
    __syncthreads();
    Z = sr[0] + sr[1] + sr[2] + sr[3];
    const float invZ = 1.f / Z;

    // partial readout: thread = (e-offset tid&15, s-slice tid>>4 of 8)
    const int eo = tid & 15, sl = tid >> 4;
    const int e = ec * 16 + eo;
    const float* tmb = g_tm + (size_t)b * Sz * EMB + e;
    float o_ = 0.f;
#pragma unroll 8
    for (int s2 = 0; s2 < 64; s2++) {
        const int s = sl * 64 + s2;
        o_ += sp[s] * tmb[(size_t)s * EMB];
    }
    s_part[sl][eo] = o_;
    __syncthreads();
    if (tid < 16) {
        float t = 0.f;
#pragma unroll
        for (int k = 0; k < 8; k++) t += s_part[k][tid];
        const int eg = ec * 16 + tid;
        g_ob[b * EMB + eg] = t * invZ + g_uH[b * EMB + eg];
    }
}

__global__ void __launch_bounds__(128) k_logits(const float* __restrict__ R,
                                                float* __restrict__ out)
{
    __shared__ u64 so2[EMB * (Bz / 2)];
    const int tid = threadIdx.x;
#pragma unroll
    for (int r = 0; r < EMB * (Bz / 2) / 128; r++) {
        const int idx = r * 128 + tid;
        const int e = idx >> 4, bb = idx & 15;
        so2[idx] = pack2(g_ob[(2 * bb) * EMB + e], g_ob[(2 * bb + 1) * EMB + e]);
    }
    __syncthreads();
    const int col = blockIdx.x * 128 + tid;
    if (col >= VOCAB) return;
    u64 acc[Bz / 2];
#pragma unroll
    for (int j = 0; j < Bz / 2; j++) acc[j] = 0ull;
#pragma unroll 8
    for (int e = 0; e < EMB; e++) {
        const u64 rd = dup2(R[(size_t)e * VOCAB + col]);
        const u64* row = so2 + e * (Bz / 2);
#pragma unroll
        for (int bb = 0; bb < Bz / 2; bb++) ffma2(acc[bb], rd, row[bb]);
    }
#pragma unroll
    for (int bb = 0; bb < Bz / 2; bb++) {
        const float2 f = unpack2(acc[bb]);
        out[(size_t)(2 * bb) * VOCAB + col]     = f.x;
        out[(size_t)(2 * bb + 1) * VOCAB + col] = f.y;
    }
}

// ============================================================
extern "C" void kernel_launch(void* const* d_in, const int* in_sizes, int n_in,
                              void* d_out, int out_size)
{
    const float* memories = (const float*)d_in[0];
    const float* stories  = (const float*)d_in[1];
    const float* smask    = (const float*)d_in[2];
    const int*   queries  = (const int*)  d_in[3];
    const int*   keys     = (const int*)  d_in[4];
    const float* emb      = (const float*)d_in[5];
    const float* mmask    = (const float*)d_in[6];
    const float* A        = (const float*)d_in[7];
    const float* Bm       = (const float*)d_in[8];
    const float* C        = (const float*)d_in[9];
    const float* v        = (const float*)d_in[10];
    const float* D        = (const float*)d_in[11];
    const float* E        = (const float*)d_in[12];
    const float* F        = (const float*)d_in[13];
    const float* w        = (const float*)d_in[14];
    const float* H        = (const float*)d_in[15];
    const float* R        = (const float*)d_in[16];
    float* out = (float*)d_out;

    cudaFuncSetAttribute(k_hmma, cudaFuncAttributeMaxDynamicSharedMemorySize, DYN_SMEM);

    k_setup<<<308, 128>>>(queries, keys, emb, mmask, C, F, H, Bm, D, E, A);
    k_hmma<<<148, 384, DYN_SMEM>>>(memories, v);
    k_align2<<<dim3(Sz / ST, Bz), 128>>>(stories, w);
    k_temporal<<<dim3(8, Bz), 128>>>(smask);
    k_logits<<<(VOCAB + 127) / 128, 128>>>(R, out);
}

// round 7
// speedup vs baseline: 2.1870x; 1.2324x over previous
#include <cuda_runtime.h>
#include <cuda_bf16.h>
#include <math.h>
#include <stdint.h>

#define Bz 32
#define Sz 512
#define NB 20
#define EMB 128
#define INNER 128
#define VOCAB 40000
#define QL 20
#define NGRP (Bz * Sz)
#define NTILES 2731            // ceil(16384 / 6)

typedef unsigned long long u64;
typedef unsigned int u32;

// ---- packed f32x2 helpers ----
__device__ __forceinline__ u64 dup2(float a) {
    u64 r; asm("mov.b64 %0, {%1, %1};" : "=l"(r) : "f"(a)); return r;
}
__device__ __forceinline__ u64 pack2(float x, float y) {
    u64 r; asm("mov.b64 %0, {%1, %2};" : "=l"(r) : "f"(x), "f"(y)); return r;
}
__device__ __forceinline__ float2 unpack2(u64 v) {
    float2 f; asm("mov.b64 {%0, %1}, %2;" : "=f"(f.x), "=f"(f.y) : "l"(v)); return f;
}
__device__ __forceinline__ void ffma2(u64& d, u64 a, u64 b) {
    asm("fma.rn.f32x2 %0, %1, %2, %0;" : "+l"(d) : "l"(a), "l"(b));
}
__device__ __forceinline__ float neg_inf_f() { return __int_as_float(0xff800000); }
__device__ __forceinline__ float tanh_fast(float x) {
    float e = __expf(2.f * x);
    return 1.f - __fdividef(2.f, e + 1.f);
}

// ---- scratch ----
__device__ float g_qc[Bz * INNER];
__device__ float g_tfv[Bz * INNER];
__device__ float g_uH[Bz * EMB];
__device__ float g_kb[NB * INNER];
__device__ u64   g_DE[EMB * INNER];
__device__ float g_tm[Bz * Sz * EMB];
__device__ float g_talign[Bz * Sz];
__device__ float g_ob[Bz * EMB];
__device__ unsigned char g_ATsw[69632];   // A^T bf16 hi/lo images, 272B row stride

// ---- warp mma helpers ----
__device__ __forceinline__ u32 smem_u32(const void* p) {
    u32 a; asm("{ .reg .u64 t; cvta.to.shared.u64 t, %1; cvt.u32.u64 %0, t; }" : "=r"(a) : "l"(p));
    return a;
}
__device__ __forceinline__ void ldsm4(u32* r, u32 addr) {
    asm volatile("ldmatrix.sync.aligned.m8n8.x4.shared.b16 {%0,%1,%2,%3}, [%4];"
        : "=r"(r[0]), "=r"(r[1]), "=r"(r[2]), "=r"(r[3]) : "r"(addr));
}
__device__ __forceinline__ void mma16816(float* d, const u32* a, u32 b0, u32 b1) {
    asm volatile("mma.sync.aligned.m16n8k16.row.col.f32.bf16.bf16.f32 "
        "{%0,%1,%2,%3}, {%4,%5,%6,%7}, {%8,%9}, {%0,%1,%2,%3};"
        : "+f"(d[0]), "+f"(d[1]), "+f"(d[2]), "+f"(d[3])
        : "r"(a[0]), "r"(a[1]), "r"(a[2]), "r"(a[3]), "r"(b0), "r"(b1));
}

#define BAR_SYNC(id, n)   asm volatile("bar.sync %0, %1;"   :: "r"(id), "r"(n) : "memory")
#define BAR_ARRIVE(id, n) asm volatile("bar.arrive %0, %1;" :: "r"(id), "r"(n) : "memory")

// smem layout (bytes)
#define IMG    34816
#define BUFSZ  69632
#define AT_OFF 139264
#define KB_OFF 208896
#define SV_OFF 220480
#define ALN_OFF 220992
#define SPB_OFF 221504
#define DYN_SMEM 222016

// ============================================================
// k_setup: prep(32) | kb(20)
// ============================================================
__global__ void __launch_bounds__(128) k_setup(
    const int* __restrict__ queries, const int* __restrict__ keys,
    const float* __restrict__ emb, const float* __restrict__ mmask,
    const float* __restrict__ C, const float* __restrict__ F,
    const float* __restrict__ H, const float* __restrict__ Bm)
{
    const int blk = blockIdx.x, tid = threadIdx.x;
    if (blk < 32) {
        const int b = blk;
        __shared__ float su[EMB];
        float u = 0.f;
#pragma unroll
        for (int q = 0; q < QL; q++)
            u += emb[(size_t)queries[b * QL + q] * EMB + tid] * mmask[q * EMB + tid];
        su[tid] = u;
        __syncthreads();
        float c = 0.f, f = 0.f, h = 0.f;
#pragma unroll 4
        for (int e = 0; e < EMB; e++) {
            const float ue = su[e];
            c += ue * C[e * INNER + tid];
            f += ue * F[e * INNER + tid];
            h += ue * H[e * EMB + tid];
        }
        g_qc[b * INNER + tid]  = c;
        g_tfv[b * INNER + tid] = f;
        g_uH[b * EMB + tid]    = h;
    } else {
        const int n = blk - 32;
        __shared__ float se[EMB];
        se[tid] = emb[(size_t)keys[n] * EMB + tid];
        __syncthreads();
        float a = 0.f;
#pragma unroll 4
        for (int e = 0; e < EMB; e++) a += se[e] * Bm[e * INNER + tid];
        g_kb[n * INNER + tid] = a;
    }
}

__global__ void __launch_bounds__(128) k_de(const float* __restrict__ D,
                                            const float* __restrict__ E)
{
    const int i = blockIdx.x * 128 + threadIdx.x;
    g_DE[i] = pack2(D[i], E[i]);
}

__global__ void __launch_bounds__(128) k_splitA(const float* __restrict__ A)
{
    const int idx = blockIdx.x * 128 + threadIdx.x;
    const int e = idx >> 7, i = idx & 127;
    const float x = A[e * 128 + i];
    const __nv_bfloat16 h = __float2bfloat16_rn(x);
    const __nv_bfloat16 l = __float2bfloat16_rn(x - __bfloat162float(h));
    *(unsigned short*)(g_ATsw + i * 272 + e * 2)       = __bfloat16_as_ushort(h);
    *(unsigned short*)(g_ATsw + IMG + i * 272 + e * 2) = __bfloat16_as_ushort(l);
}

// ============================================================
// k_hmma: persistent, warp-specialized
// ============================================================
__device__ __forceinline__ void cvt_store(char* bufp, int r, int c16, float4 x)
{
    const __nv_bfloat16 h0 = __float2bfloat16_rn(x.x);
    const __nv_bfloat16 h1 = __float2bfloat16_rn(x.y);
    const __nv_bfloat16 h2 = __float2bfloat16_rn(x.z);
    const __nv_bfloat16 h3 = __float2bfloat16_rn(x.w);
    const __nv_bfloat16 l0 = __float2bfloat16_rn(x.x - __bfloat162float(h0));
    const __nv_bfloat16 l1 = __float2bfloat16_rn(x.y - __bfloat162float(h1));
    const __nv_bfloat16 l2 = __float2bfloat16_rn(x.z - __bfloat162float(h2));
    const __nv_bfloat16 l3 = __float2bfloat16_rn(x.w - __bfloat162float(h3));
    uint2 hp, lp;
    hp.x = (u32)__bfloat16_as_ushort(h0) | ((u32)__bfloat16_as_ushort(h1) << 16);
    hp.y = (u32)__bfloat16_as_ushort(h2) | ((u32)__bfloat16_as_ushort(h3) << 16);
    lp.x = (u32)__bfloat16_as_ushort(l0) | ((u32)__bfloat16_as_ushort(l1) << 16);
    lp.y = (u32)__bfloat16_as_ushort(l2) | ((u32)__bfloat16_as_ushort(l3) << 16);
    *(uint2*)(bufp + r * 272 + c16 * 8)       = hp;
    *(uint2*)(bufp + IMG + r * 272 + c16 * 8) = lp;
}

// batched-MLP producer: 5 batches of 6 register-staged float4 loads
__device__ __forceinline__ void load_tile(char* sm, const float* __restrict__ mem,
                                          int Gt0, int ng, int buf, int ptid)
{
    char* bufp = sm + buf * BUFSZ;
    const float* src = mem + (size_t)Gt0 * (NB * EMB);
    if (ng == 6) {
#pragma unroll
        for (int c = 0; c < 5; c++) {
            float4 x[6];
#pragma unroll
            for (int j = 0; j < 6; j++) {
                const int idx = ptid + (c * 6 + j) * 128;
                x[j] = *((const float4*)(src + (size_t)(idx >> 5) * 128) + (idx & 31));
            }
#pragma unroll
            for (int j = 0; j < 6; j++) {
                const int idx = ptid + (c * 6 + j) * 128;
                cvt_store(bufp, idx >> 5, idx & 31, x[j]);
            }
        }
    } else {
        const int iters = ng * 20 * 32;
        for (int idx = ptid; idx < iters; idx += 128) {
            const float4 x = *((const float4*)(src + (size_t)(idx >> 5) * 128) + (idx & 31));
            cvt_store(bufp, idx >> 5, idx & 31, x);
        }
    }
}

__global__ void __launch_bounds__(384, 1) k_hmma(const float* __restrict__ mem,
                                                 const float* __restrict__ v)
{
    extern __shared__ char sm[];
    const int tid = threadIdx.x, w = tid >> 5, lane = tid & 31;
    const u32 smb = smem_u32(sm);

    {
        const uint4* src = (const uint4*)g_ATsw;
        uint4* dst = (uint4*)(sm + AT_OFF);
        for (int k = tid; k < BUFSZ / 16; k += 384) dst[k] = src[k];
    }
    for (int idx = tid; idx < 20 * 128; idx += 384) {
        const int n = idx >> 7, e = idx & 127;
        ((float*)(sm + KB_OFF))[n * 132 + e] = g_kb[n * 128 + e];
    }
    if (tid < 128) ((float*)(sm + SV_OFF))[tid] = v[tid];
    __syncthreads();

    if (w >= 8) {
        // ---------------- producers ----------------
        const int ptid = tid - 256;
        int lt = 0;
        for (int tt = blockIdx.x; tt < NTILES; tt += gridDim.x, lt++) {
            if (lt >= 2) BAR_SYNC(3 + (lt & 1), 384);
            const int Gt0 = tt * 6;
            const int ng = min(6, NGRP - Gt0);
            load_tile(sm, mem, Gt0, ng, lt & 1, ptid);
            BAR_ARRIVE(1 + (lt & 1), 384);
        }
        return;
    }

    // ---------------- consumers ----------------
    float* aln = (float*)(sm + ALN_OFF);
    float* spb = (float*)(sm + SPB_OFF);
    const float* kbs = (const float*)(sm + KB_OFF);
    const float* sv  = (const float*)(sm + SV_OFF);

    const u32 arow = (lane & 7) + ((lane >> 3) & 1) * 8;
    const u32 acol = (lane >> 4) * 16;
    const u32 brow = (lane & 7) + ((lane >> 4) & 1) * 8;
    const u32 bcol = ((lane >> 3) & 1) * 16;
    const u32 abase0 = smb + (w * 16 + arow) * 272 + acol;
    const u32 bbase  = smb + AT_OFF + brow * 272 + bcol;

    int lt = 0;
    for (int tt = blockIdx.x; tt < NTILES; tt += gridDim.x, lt++) {
        BAR_SYNC(1 + (lt & 1), 384);

        // ---- mma: three independent-chain passes per k-step ----
        float acc[16][4];
#pragma unroll
        for (int nt = 0; nt < 16; nt++) { acc[nt][0] = acc[nt][1] = acc[nt][2] = acc[nt][3] = 0.f; }
        const u32 abase = abase0 + (lt & 1) * BUFSZ;
#pragma unroll
        for (int k = 0; k < 8; k++) {
            u32 ahi[4], alo[4], bhi[8][4];
            const u32 aaddr = abase + k * 32;
            ldsm4(ahi, aaddr);
            ldsm4(alo, aaddr + IMG);
#pragma unroll
            for (int p = 0; p < 8; p++) {
                ldsm4(bhi[p], bbase + p * (16 * 272) + k * 32);
                mma16816(acc[2 * p],     ahi, bhi[p][0], bhi[p][1]);
                mma16816(acc[2 * p + 1], ahi, bhi[p][2], bhi[p][3]);
            }
#pragma unroll
            for (int p = 0; p < 8; p++) {
                mma16816(acc[2 * p],     alo, bhi[p][0], bhi[p][1]);
                mma16816(acc[2 * p + 1], alo, bhi[p][2], bhi[p][3]);
            }
#pragma unroll
            for (int p = 0; p < 8; p++) {
                u32 blo[4];
                ldsm4(blo, bbase + p * (16 * 272) + k * 32 + IMG);
                mma16816(acc[2 * p],     ahi, blo[0], blo[1]);
                mma16816(acc[2 * p + 1], ahi, blo[2], blo[3]);
            }
        }

        // ---- epilogue ----
        const int Gt0 = tt * 6;
        const int ng = min(6, NGRP - Gt0);
        const int rows = ng * 20;
        const int rA = (w << 4) + (lane >> 2);
        const int rB = rA + 8;
        const int gA = min(rA / 20, ng - 1), gB = min(rB / 20, ng - 1);
        const int nA = rA % 20, nB2 = rB % 20;
        const float* qA = g_qc + (size_t)((Gt0 + gA) >> 9) * 128;
        const float* qB = g_qc + (size_t)((Gt0 + gB) >> 9) * 128;
        const float* kA = kbs + nA * 132;
        const float* kB = kbs + nB2 * 132;
        const int cb = 2 * (lane & 3);
        float sumA = 0.f, sumB = 0.f;
#pragma unroll
        for (int nt = 0; nt < 16; nt++) {
            const int c0 = nt * 8 + cb;
            const float2 ka  = *(const float2*)(kA + c0);
            const float2 kb2 = *(const float2*)(kB + c0);
            const float2 qa  = *(const float2*)(qA + c0);
            const float2 qb  = *(const float2*)(qB + c0);
            const float2 vv  = *(const float2*)(sv + c0);
            sumA += vv.x * tanh_fast(acc[nt][0] + ka.x + qa.x);
            sumA += vv.y * tanh_fast(acc[nt][1] + ka.y + qa.y);
            sumB += vv.x * tanh_fast(acc[nt][2] + kb2.x + qb.x);
            sumB += vv.y * tanh_fast(acc[nt][3] + kb2.y + qb.y);
        }
        sumA += __shfl_xor_sync(0xffffffffu, sumA, 1);
        sumA += __shfl_xor_sync(0xffffffffu, sumA, 2);
        sumB += __shfl_xor_sync(0xffffffffu, sumB, 1);
        sumB += __shfl_xor_sync(0xffffffffu, sumB, 2);
        if ((lane & 3) == 0) { aln[rA] = sumA; aln[rB] = sumB; }
        BAR_SYNC(5, 256);

        if (tid < rows) {
            const int gb = (tid / 20) * 20;
            float mx = -1e30f;
#pragma unroll
            for (int n2 = 0; n2 < 20; n2++) mx = fmaxf(mx, aln[gb + n2]);
            float Z = 0.f;
#pragma unroll
            for (int n2 = 0; n2 < 20; n2++) Z += __expf(aln[gb + n2] - mx);
            spb[tid] = __expf(aln[tid] - mx) / Z;
        }
        BAR_SYNC(5, 256);

        {   // tm readback from ORIGINAL fp32 memories (L1/L2-resident) — exact
            const float* msrc = mem + (size_t)Gt0 * (NB * EMB);
            const int e = tid & 127, gh = tid >> 7;
#pragma unroll
            for (int g2 = 0; g2 < 3; g2++) {
                const int g = gh * 3 + g2;
                if (g < ng) {
                    float accv = 0.f;
                    const int r0 = g * 20;
#pragma unroll
                    for (int n2 = 0; n2 < 20; n2++)
                        accv += spb[r0 + n2] * msrc[(size_t)(r0 + n2) * 128 + e];
                    g_tm[(size_t)(Gt0 + g) * 128 + e] = accv;
                }
            }
        }
        BAR_ARRIVE(3 + (lt & 1), 384);
    }
}

// ============================================================
#define ST 16
__global__ void __launch_bounds__(128) k_align2(
    const float* __restrict__ stories, const float* __restrict__ w)
{
    const int b = blockIdx.y, s0 = blockIdx.x * ST;
    const int tid = threadIdx.x, lane = tid & 31, wid = tid >> 5;
    __shared__ u64 sp[EMB * ST];
    __shared__ float s_part[4 * ST];
#pragma unroll
    for (int si = 0; si < ST; si++) {
        const size_t base = ((size_t)(b * Sz + s0 + si)) * EMB + tid;
        sp[tid * ST + si] = pack2(g_tm[base], stories[base]);
    }
    __syncthreads();
    u64 acc[ST];
#pragma unroll
    for (int si = 0; si < ST; si++) acc[si] = 0ull;
#pragma unroll 2
    for (int e = 0; e < EMB; e++) {
        const u64 de = g_DE[e * INNER + tid];
        const ulonglong2* row = (const ulonglong2*)(sp + e * ST);
#pragma unroll
        for (int k = 0; k < ST / 2; k++) {
            const ulonglong2 m = row[k];
            ffma2(acc[2 * k],     m.x, de);
            ffma2(acc[2 * k + 1], m.y, de);
        }
    }
    const float tfi = g_tfv[b * INNER + tid];
    const float wi  = w[tid];
    float tv[ST];
#pragma unroll
    for (int si = 0; si < ST; si++) {
        const float2 f = unpack2(acc[si]);
        float t = wi * tanh_fast(f.x + f.y + tfi);
#pragma unroll
        for (int o = 16; o > 0; o >>= 1) t += __shfl_xor_sync(0xffffffffu, t, o);
        tv[si] = t;
    }
    if (lane == 0) {
#pragma unroll
        for (int si = 0; si < ST; si++) s_part[wid * ST + si] = tv[si];
    }
    __syncthreads();
    if (tid < ST)
        g_talign[b * Sz + s0 + tid] =
            s_part[tid] + s_part[ST + tid] + s_part[2 * ST + tid] + s_part[3 * ST + tid];
}

// ============================================================
__global__ void __launch_bounds__(128) k_temporal(const float* __restrict__ mask)
{
    const int ec = blockIdx.x, b = blockIdx.y;
    const int tid = threadIdx.x, lane = tid & 31, wid = tid >> 5;
    __shared__ float sp[Sz];
    __shared__ float sr[4];
    __shared__ float s_part[8][16];

    float vals[4];
    float mx = neg_inf_f();
#pragma unroll
    for (int r = 0; r < 4; r++) {
        const int s = r * 128 + tid;
        const float ta = g_talign[b * Sz + s];
        const float m  = mask[b * Sz + s];
        const float ml = (m != 0.f) ? ta * m : neg_inf_f();
        vals[r] = ml;
        mx = fmaxf(mx, ml);
    }
#pragma unroll
    for (int o = 16; o > 0; o >>= 1) mx = fmaxf(mx, __shfl_xor_sync(0xffffffffu, mx, o));
    if (lane == 0) sr[wid] = mx;
    __syncthreads();
    mx = fmaxf(fmaxf(sr[0], sr[1]), fmaxf(sr[2], sr[3]));
    __syncthreads();
    float Z = 0.f;
#pragma unroll
    for (int r = 0; r < 4; r++) {
        const float ev = __expf(vals[r] - mx);
        sp[r * 128 + tid] = ev;
        Z += ev;
    }
#pragma unroll
    for (int o = 16; o > 0; o >>= 1) Z += __shfl_xor_sync(0xffffffffu, Z, o);
    if (lane == 0) sr[wid] = Z;
    __syncthreads();
    Z = sr[0] + sr[1] + sr[2] + sr[3];
    const float invZ = 1.f / Z;

    const int eo = tid & 15, sl = tid >> 4;
    const int e = ec * 16 + eo;
    const float* tmb = g_tm + (size_t)b * Sz * EMB + e;
    float o_ = 0.f;
#pragma unroll 8
    for (int s2 = 0; s2 < 64; s2++) {
        const int s = sl * 64 + s2;
        o_ += sp[s] * tmb[(size_t)s * EMB];
    }
    s_part[sl][eo] = o_;
    __syncthreads();
    if (tid < 16) {
        float t = 0.f;
#pragma unroll
        for (int k = 0; k < 8; k++) t += s_part[k][tid];
        const int eg = ec * 16 + tid;
        g_ob[b * EMB + eg] = t * invZ + g_uH[b * EMB + eg];
    }
}

__global__ void __launch_bounds__(128) k_logits(const float* __restrict__ R,
                                                float* __restrict__ out)
{
    __shared__ u64 so2[EMB * (Bz / 2)];
    const int tid = threadIdx.x;
#pragma unroll
    for (int r = 0; r < EMB * (Bz / 2) / 128; r++) {
        const int idx = r * 128 + tid;
        const int e = idx >> 4, bb = idx & 15;
        so2[idx] = pack2(g_ob[(2 * bb) * EMB + e], g_ob[(2 * bb + 1) * EMB + e]);
    }
    __syncthreads();
    const int col = blockIdx.x * 128 + tid;
    if (col >= VOCAB) return;
    u64 acc[Bz / 2];
#pragma unroll
    for (int j = 0; j < Bz / 2; j++) acc[j] = 0ull;
#pragma unroll 8
    for (int e = 0; e < EMB; e++) {
        const u64 rd = dup2(R[(size_t)e * VOCAB + col]);
        const u64* row = so2 + e * (Bz / 2);
#pragma unroll
        for (int bb = 0; bb < Bz / 2; bb++) ffma2(acc[bb], rd, row[bb]);
    }
#pragma unroll
    for (int bb = 0; bb < Bz / 2; bb++) {
        const float2 f = unpack2(acc[bb]);
        out[(size_t)(2 * bb) * VOCAB + col]     = f.x;
        out[(size_t)(2 * bb + 1) * VOCAB + col] = f.y;
    }
}

// ============================================================
extern "C" void kernel_launch(void* const* d_in, const int* in_sizes, int n_in,
                              void* d_out, int out_size)
{
    const float* memories = (const float*)d_in[0];
    const float* stories  = (const float*)d_in[1];
    const float* smask    = (const float*)d_in[2];
    const int*   queries  = (const int*)  d_in[3];
    const int*   keys     = (const int*)  d_in[4];
    const float* emb      = (const float*)d_in[5];
    const float* mmask    = (const float*)d_in[6];
    const float* A        = (const float*)d_in[7];
    const float* Bm       = (const float*)d_in[8];
    const float* C        = (const float*)d_in[9];
    const float* v        = (const float*)d_in[10];
    const float* D        = (const float*)d_in[11];
    const float* E        = (const float*)d_in[12];
    const float* F        = (const float*)d_in[13];
    const float* w        = (const float*)d_in[14];
    const float* H        = (const float*)d_in[15];
    const float* R        = (const float*)d_in[16];
    float* out = (float*)d_out;

    cudaFuncSetAttribute(k_hmma, cudaFuncAttributeMaxDynamicSharedMemorySize, DYN_SMEM);

    // k_hmma deliberately placed at launch index 3 (the slot ncu captures)
    k_setup<<<52, 128>>>(queries, keys, emb, mmask, C, F, H, Bm);
    k_de<<<EMB * INNER / 128, 128>>>(D, E);
    k_splitA<<<EMB * INNER / 128, 128>>>(A);
    k_hmma<<<148, 384, DYN_SMEM>>>(memories, v);
    k_align2<<<dim3(Sz / ST, Bz), 128>>>(stories, w);
    k_temporal<<<dim3(8, Bz), 128>>>(smask);
    k_logits<<<(VOCAB + 127) / 128, 128>>>(R, out);
}